// round 13
// baseline (speedup 1.0000x reference)
#include <cuda_runtime.h>
#include <cuda_fp16.h>
#include <cstdint>

// Problem constants
#define Nn    50000
#define Dd    128
#define Rr    10
#define Ee    800000
#define NSEL  8192
#define NCc   12
#define NTILE 391                 // ceil(Nn/128)
#define NG    782                 // ceil(Nn/64) src groups
#define NBKT  (Rr * NG)
#define SLOTS (Rr + 1)            // 10 relations + root

// ftg_h smem: A half[128][136] + B half[128][136] + Ch f32[64][132]
#define SMH_A_BYTES (128 * 136 * 2)     // 34816
#define CH_BYTES    (64 * 132 * 4)      // 33792
#define SMH_TOTAL   (2 * SMH_A_BYTES + CH_BYTES)   // 103424
#define CH_STRIDE   132

// mega-kernel block ranges
#define NB_PROJ  354      // 157 + 118 + 79
#define NB_COPY  6250     // Nn*Dd/4 / 256
#define NB_CNT   3125     // Ee / 256

// k_setup: build-W blocks (1024 thr) + 1 scan block
#define NB_BW    176      // SLOTS*Dd*Dd / 1024 = 180224/1024

// ---------------- device scratch ----------------
__device__ __half g_xh[Nn * Dd];              // node features, fp16
__device__ float  g_acc[Nn * Dd];             // conv accumulator (fp32)
__device__ __half g_Wh[2 * SLOTS * Dd * Dd];  // both layers' W^T [layer][slot][n][k]
__device__ int    g_icnt[Rr * Nn];
__device__ float  g_hsel[NSEL * Dd];
__device__ int    g_bcnt[NBKT];
__device__ int    g_bcur[NBKT];
__device__ int    g_boff[NBKT + 1];
__device__ int    g_bsrc[Ee];
__device__ int    g_bdst[Ee];
__device__ float  g_bw[Ee];

// ---------------- helpers ----------------
__device__ __forceinline__ unsigned f2tf(float f) {
    unsigned u;
    asm("cvt.rna.tf32.f32 %0, %1;" : "=r"(u) : "f"(f));
    return u;
}

__device__ __forceinline__ void mma_tf32(float c[4], const unsigned a[4], const unsigned b[2]) {
    asm volatile("mma.sync.aligned.m16n8k8.row.col.f32.tf32.tf32.f32 "
                 "{%0,%1,%2,%3}, {%4,%5,%6,%7}, {%8,%9}, {%0,%1,%2,%3};"
                 : "+f"(c[0]), "+f"(c[1]), "+f"(c[2]), "+f"(c[3])
                 : "r"(a[0]), "r"(a[1]), "r"(a[2]), "r"(a[3]), "r"(b[0]), "r"(b[1]));
}

__device__ __forceinline__ void mma_f16(float c[4], unsigned a0, unsigned a1,
                                        unsigned a2, unsigned a3,
                                        unsigned b0, unsigned b1) {
    asm volatile("mma.sync.aligned.m16n8k16.row.col.f32.f16.f16.f32 "
                 "{%0,%1,%2,%3}, {%4,%5,%6,%7}, {%8,%9}, {%0,%1,%2,%3};"
                 : "+f"(c[0]), "+f"(c[1]), "+f"(c[2]), "+f"(c[3])
                 : "r"(a0), "r"(a1), "r"(a2), "r"(a3), "r"(b0), "r"(b1));
}

__device__ __forceinline__ void cp16(void* smem, const void* g, int srcsize) {
    unsigned a = (unsigned)__cvta_generic_to_shared(smem);
    asm volatile("cp.async.ca.shared.global [%0], [%1], 16, %2;"
                 :: "r"(a), "l"(g), "r"(srcsize));
}

__device__ __forceinline__ void ldsm4(unsigned& r0, unsigned& r1, unsigned& r2, unsigned& r3,
                                      uint32_t addr) {
    asm volatile("ldmatrix.sync.aligned.m8n8.x4.shared.b16 {%0,%1,%2,%3}, [%4];"
                 : "=r"(r0), "=r"(r1), "=r"(r2), "=r"(r3) : "r"(addr));
}

__device__ __forceinline__ uint32_t sma(const void* p) {
    return (uint32_t)__cvta_generic_to_shared(p);
}

// ---------------- small kernels ----------------
__global__ void k_zero() {
    int i = blockIdx.x * blockDim.x + threadIdx.x;
    if (i < Rr * Nn) g_icnt[i] = 0;
    if (i < NBKT) { g_bcnt[i] = 0; g_bcur[i] = 0; }
}

// fused: builds both layers' W^T (fp16) AND runs the bucket scan in the last block.
// grid = (NB_BW + 1, 2), block = 1024.
__global__ void k_setup(const float* __restrict__ comp1, const float* __restrict__ bases1,
                        const float* __restrict__ root1,
                        const float* __restrict__ comp2, const float* __restrict__ bases2,
                        const float* __restrict__ root2) {
    int t = threadIdx.x;
    if (blockIdx.x == NB_BW) {
        if (blockIdx.y != 0) return;
        // ---- warp-shuffle two-level scan over NBKT bucket counts -> g_boff ----
        __shared__ int wsum[32];
        int lane = t & 31, wid = t >> 5;
        int cnt[8];
        int s = 0;
#pragma unroll
        for (int j = 0; j < 8; j++) {
            int b = t * 8 + j;
            cnt[j] = (b < NBKT) ? g_bcnt[b] : 0;
            s += cnt[j];
        }
        int incl = s;
#pragma unroll
        for (int o = 1; o < 32; o <<= 1) {
            int v = __shfl_up_sync(0xffffffffu, incl, o);
            if (lane >= o) incl += v;
        }
        if (lane == 31) wsum[wid] = incl;
        __syncthreads();
        if (wid == 0) {
            int v = wsum[lane];
            int iv = v;
#pragma unroll
            for (int o = 1; o < 32; o <<= 1) {
                int u = __shfl_up_sync(0xffffffffu, iv, o);
                if (lane >= o) iv += u;
            }
            wsum[lane] = iv - v;
            if (lane == 31) g_boff[NBKT] = iv;
        }
        __syncthreads();
        int run = wsum[wid] + (incl - s);
#pragma unroll
        for (int j = 0; j < 8; j++) {
            int b = t * 8 + j;
            if (b < NBKT) { g_boff[b] = run; run += cnt[j]; }
        }
        return;
    }
    // ---- build W element ----
    int i = blockIdx.x * 1024 + t;
    int layer = blockIdx.y;
    const float* comp  = layer ? comp2  : comp1;
    const float* bases = layer ? bases2 : bases1;
    const float* root  = layer ? root2  : root1;
    int slot = i >> 14;
    int idx  = i & 16383;          // n*128 + k
    int n = idx >> 7, k = idx & 127;
    int src = k * 128 + n;
    float v;
    if (slot < Rr) {
        v = 0.f;
#pragma unroll
        for (int b = 0; b < 4; b++)
            v += comp[slot * 4 + b] * bases[b * Dd * Dd + src];
    } else {
        v = root[src];
    }
    g_Wh[layer * SLOTS * Dd * Dd + i] = __float2half_rn(v);
}

// places edges AND computes the mean weight inline
__global__ void k_place(const int* __restrict__ ei, const int* __restrict__ et) {
    int e = blockIdx.x * blockDim.x + threadIdx.x;
    if (e >= Ee) return;
    int r = et[e];
    int s = ei[e], t = ei[Ee + e];
    int key = r * NG + (s >> 6);
    int pos = g_boff[key] + atomicAdd(&g_bcur[key], 1);
    g_bsrc[pos] = s;
    g_bdst[pos] = t;
    g_bw[pos]   = 1.0f / fmaxf((float)g_icnt[r * Nn + t], 1.0f);
}

// one warp per node: LayerNorm (+optional ReLU) -> g_xh (fp16); zeroes acc
__global__ void k_ln(const float* __restrict__ g, const float* __restrict__ b, int relu) {
    int gt = blockIdx.x * blockDim.x + threadIdx.x;
    int node = gt >> 5;
    if (node >= Nn) return;
    int lane = gt & 31;
    float4 v = ((const float4*)g_acc)[node * 32 + lane];
    float s = v.x + v.y + v.z + v.w;
    float q = v.x * v.x + v.y * v.y + v.z * v.z + v.w * v.w;
#pragma unroll
    for (int o = 16; o; o >>= 1) {
        s += __shfl_xor_sync(0xffffffffu, s, o);
        q += __shfl_xor_sync(0xffffffffu, q, o);
    }
    float mean = s * (1.f / 128.f);
    float var  = q * (1.f / 128.f) - mean * mean;
    float rstd = rsqrtf(var + 1e-5f);
    float4 gg = ((const float4*)g)[lane];
    float4 bb = ((const float4*)b)[lane];
    float4 o4;
    o4.x = (v.x - mean) * rstd * gg.x + bb.x;
    o4.y = (v.y - mean) * rstd * gg.y + bb.y;
    o4.z = (v.z - mean) * rstd * gg.z + bb.z;
    o4.w = (v.w - mean) * rstd * gg.w + bb.w;
    if (relu) {
        o4.x = fmaxf(o4.x, 0.f); o4.y = fmaxf(o4.y, 0.f);
        o4.z = fmaxf(o4.z, 0.f); o4.w = fmaxf(o4.w, 0.f);
    }
    __half2 p0 = __halves2half2(__float2half_rn(o4.x), __float2half_rn(o4.y));
    __half2 p1 = __halves2half2(__float2half_rn(o4.z), __float2half_rn(o4.w));
    ((uint2*)g_xh)[node * 32 + lane] = make_uint2(*(unsigned*)&p0, *(unsigned*)&p1);
    ((float4*)g_acc)[node * 32 + lane] = make_float4(0.f, 0.f, 0.f, 0.f);
}

__global__ void k_final(const float* __restrict__ W, const float* __restrict__ b,
                        float* __restrict__ out) {
    int gt = blockIdx.x * blockDim.x + threadIdx.x;
    if (gt >= NSEL * NCc) return;
    int i = gt / NCc, c = gt % NCc;
    const float* hr = g_hsel + i * Dd;
    float s = b[c];
#pragma unroll 8
    for (int k = 0; k < Dd; k++) s += hr[k] * W[k * NCc + c];
    out[gt] = s;
}

// ---------------- mega kernel: proj (3 segs) || fallback-copy+acc-zero || edge-count --
__global__ void __launch_bounds__(256)
k_mega(const float* A0, const float* W0, const float* b0, const int* x0, int M0, int K0,
       const float* A1, const float* W1, const float* b1, const int* x1, int M1, int K1,
       const float* A2, const float* W2, const float* b2, const int* x2, int M2, int K2,
       const float* __restrict__ fallback,
       const int* __restrict__ ei, const int* __restrict__ et) {
    int blk = blockIdx.x;
    int tid = threadIdx.x;

    if (blk >= NB_PROJ) {
        if (blk < NB_PROJ + NB_COPY) {
            int i = (blk - NB_PROJ) * 256 + tid;
            if (i < Nn * Dd / 4) {
                if (i >= 45000 * 32) {
                    float4 v = ((const float4*)fallback)[i];
                    __half2 p0 = __halves2half2(__float2half_rn(v.x), __float2half_rn(v.y));
                    __half2 p1 = __halves2half2(__float2half_rn(v.z), __float2half_rn(v.w));
                    ((uint2*)g_xh)[i] = make_uint2(*(unsigned*)&p0, *(unsigned*)&p1);
                }
                ((float4*)g_acc)[i] = make_float4(0.f, 0.f, 0.f, 0.f);
            }
        } else {
            int e = (blk - NB_PROJ - NB_COPY) * 256 + tid;
            if (e < Ee) {
                int r = et[e];
                atomicAdd(&g_icnt[r * Nn + ei[Ee + e]], 1);
                atomicAdd(&g_bcnt[r * NG + (ei[e] >> 6)], 1);
            }
        }
        return;
    }

    // ---- projection GEMM segment ----
    const float *A, *B, *bias;
    const int* rowIdx;
    int M, K, row0;
    if (blk < 157)      { A = A0; B = W0; bias = b0; rowIdx = x0; M = M0; K = K0; row0 = blk * 128; }
    else if (blk < 275) { A = A1; B = W1; bias = b1; rowIdx = x1; M = M1; K = K1; row0 = (blk - 157) * 128; }
    else                { A = A2; B = W2; bias = b2; rowIdx = x2; M = M2; K = K2; row0 = (blk - 275) * 128; }

    __shared__ unsigned As[128][36];
    __shared__ unsigned Bs[32][136];
    float acc[2][8][4];
#pragma unroll
    for (int mt = 0; mt < 2; mt++)
#pragma unroll
        for (int nt = 0; nt < 8; nt++)
#pragma unroll
            for (int q = 0; q < 4; q++) acc[mt][nt][q] = 0.f;

    int lane = tid & 31, wid = tid >> 5;
    int wm = (wid >> 1) * 32;
    int wn = (wid & 1) * 64;

    for (int kb = 0; kb < K; kb += 32) {
#pragma unroll
        for (int it = 0; it < 4; it++) {
            int idx = tid + it * 256;
            int m = idx >> 3;
            int kq = (idx & 7) * 4;
            float4 v = make_float4(0.f, 0.f, 0.f, 0.f);
            int row = row0 + m;
            if (row < M) v = *(const float4*)&A[(size_t)row * K + kb + kq];
            As[m][kq + 0] = f2tf(v.x); As[m][kq + 1] = f2tf(v.y);
            As[m][kq + 2] = f2tf(v.z); As[m][kq + 3] = f2tf(v.w);
        }
#pragma unroll
        for (int it = 0; it < 4; it++) {
            int idx = tid + it * 256;
            int k = idx >> 5;
            int nq = (idx & 31) * 4;
            float4 v = *(const float4*)&B[(size_t)(kb + k) * 128 + nq];
            Bs[k][nq + 0] = f2tf(v.x); Bs[k][nq + 1] = f2tf(v.y);
            Bs[k][nq + 2] = f2tf(v.z); Bs[k][nq + 3] = f2tf(v.w);
        }
        __syncthreads();
#pragma unroll
        for (int ks = 0; ks < 4; ks++) {
            int k0 = ks * 8;
            unsigned af[2][4];
#pragma unroll
            for (int mt = 0; mt < 2; mt++) {
                int r = wm + mt * 16 + (lane >> 2);
                int c = k0 + (lane & 3);
                af[mt][0] = As[r][c];     af[mt][1] = As[r + 8][c];
                af[mt][2] = As[r][c + 4]; af[mt][3] = As[r + 8][c + 4];
            }
#pragma unroll
            for (int nt = 0; nt < 8; nt++) {
                unsigned bf[2];
                int br = k0 + (lane & 3);
                int bc = wn + nt * 8 + (lane >> 2);
                bf[0] = Bs[br][bc];
                bf[1] = Bs[br + 4][bc];
                mma_tf32(acc[0][nt], af[0], bf);
                mma_tf32(acc[1][nt], af[1], bf);
            }
        }
        __syncthreads();
    }

#pragma unroll
    for (int mt = 0; mt < 2; mt++) {
#pragma unroll
        for (int h = 0; h < 2; h++) {
            int row = row0 + wm + mt * 16 + (lane >> 2) + h * 8;
            if (row >= M) continue;
            int cr = rowIdx[row];
#pragma unroll
            for (int nt = 0; nt < 8; nt++) {
                int col = wn + nt * 8 + 2 * (lane & 3);
                float v0 = acc[mt][nt][h * 2 + 0] + bias[col];
                float v1 = acc[mt][nt][h * 2 + 1] + bias[col + 1];
                __half2 p = __halves2half2(__float2half_rn(v0), __float2half_rn(v1));
                *(unsigned*)&g_xh[(size_t)cr * 128 + col] = *(unsigned*)&p;
            }
        }
    }
}

// ---------------- classifier GEMM: half input (exact cvt), tf32 math, f32 out ----
__global__ void __launch_bounds__(256)
cgemm(const int* __restrict__ aIdx, const float* __restrict__ B,
      const float* __restrict__ bias) {
    int row0 = blockIdx.x * 128;
    __shared__ unsigned As[128][36];
    __shared__ unsigned Bs[32][136];
    float acc[2][8][4];
#pragma unroll
    for (int mt = 0; mt < 2; mt++)
#pragma unroll
        for (int nt = 0; nt < 8; nt++)
#pragma unroll
            for (int q = 0; q < 4; q++) acc[mt][nt][q] = 0.f;

    int tid = threadIdx.x;
    int lane = tid & 31, wid = tid >> 5;
    int wm = (wid >> 1) * 32;
    int wn = (wid & 1) * 64;

    for (int kb = 0; kb < 128; kb += 32) {
#pragma unroll
        for (int it = 0; it < 4; it++) {
            int idx = tid + it * 256;
            int m = idx >> 3;
            int kq = (idx & 7) * 4;
            int row = row0 + m;
            int ar = aIdx[row];
            const __half* src = &g_xh[(size_t)ar * 128 + kb + kq];
            As[m][kq + 0] = f2tf(__half2float(src[0]));
            As[m][kq + 1] = f2tf(__half2float(src[1]));
            As[m][kq + 2] = f2tf(__half2float(src[2]));
            As[m][kq + 3] = f2tf(__half2float(src[3]));
        }
#pragma unroll
        for (int it = 0; it < 4; it++) {
            int idx = tid + it * 256;
            int k = idx >> 5;
            int nq = (idx & 31) * 4;
            float4 v = *(const float4*)&B[(size_t)(kb + k) * 128 + nq];
            Bs[k][nq + 0] = f2tf(v.x); Bs[k][nq + 1] = f2tf(v.y);
            Bs[k][nq + 2] = f2tf(v.z); Bs[k][nq + 3] = f2tf(v.w);
        }
        __syncthreads();
#pragma unroll
        for (int ks = 0; ks < 4; ks++) {
            int k0 = ks * 8;
            unsigned af[2][4];
#pragma unroll
            for (int mt = 0; mt < 2; mt++) {
                int r = wm + mt * 16 + (lane >> 2);
                int c = k0 + (lane & 3);
                af[mt][0] = As[r][c];     af[mt][1] = As[r + 8][c];
                af[mt][2] = As[r][c + 4]; af[mt][3] = As[r + 8][c + 4];
            }
#pragma unroll
            for (int nt = 0; nt < 8; nt++) {
                unsigned bf[2];
                int br = k0 + (lane & 3);
                int bc = wn + nt * 8 + (lane >> 2);
                bf[0] = Bs[br][bc];
                bf[1] = Bs[br + 4][bc];
                mma_tf32(acc[0][nt], af[0], bf);
                mma_tf32(acc[1][nt], af[1], bf);
            }
        }
        __syncthreads();
    }

#pragma unroll
    for (int mt = 0; mt < 2; mt++) {
#pragma unroll
        for (int h = 0; h < 2; h++) {
            int row = row0 + wm + mt * 16 + (lane >> 2) + h * 8;
#pragma unroll
            for (int nt = 0; nt < 8; nt++) {
                int col = wn + nt * 8 + 2 * (lane & 3);
                float v0 = fmaxf(acc[mt][nt][h * 2 + 0] + bias[col], 0.f);
                float v1 = fmaxf(acc[mt][nt][h * 2 + 1] + bias[col + 1], 0.f);
                *(float2*)&g_hsel[(size_t)row * 128 + col] = make_float2(v0, v1);
            }
        }
    }
}

// ---------------- fp16 fused GEMM + scatter: ONE block per tile, loop over slots ----
// A loaded once. Per slot: B prefetched (under previous epilogue, own Ch buffer),
// MMA with fresh acc, two-phase 64-row epilogue (or root add). grid = NTILE.
__global__ void __launch_bounds__(256, 2)
ftg_h(const float* __restrict__ bias, int layer) {
    extern __shared__ __align__(16) char dsm[];
    __half (*As)[136] = (__half(*)[136])dsm;
    __half (*Bs)[136] = (__half(*)[136])(dsm + SMH_A_BYTES);
    float  (*Ch)[CH_STRIDE] = (float(*)[CH_STRIDE])(dsm + 2 * SMH_A_BYTES);  // 64 rows

    int tile = blockIdx.x;
    int row0 = tile * 128;
    int tid = threadIdx.x;
    int lane = tid & 31, wid = tid >> 5;
    int wm = (wid >> 1) * 32;
    int wn = (wid & 1) * 64;

    // slot list: non-empty relations + root (always last)
    int slots[SLOTS];
    int ns = 0;
    for (int r = 0; r < Rr; r++) {
        int b0 = r * NG + tile * 2;
        if (g_boff[b0 + 2] > g_boff[b0]) slots[ns++] = r;
    }
    slots[ns++] = Rr;

    const __half* Wbase = g_Wh + (size_t)layer * SLOTS * Dd * Dd;

    // A tile (once) + first B
#pragma unroll
    for (int it = 0; it < 8; it++) {
        int idx = tid + it * 256;
        int m = idx >> 4, c8 = (idx & 15) * 8;
        int gr = row0 + m;
        cp16(&As[m][c8], &g_xh[(size_t)gr * 128 + c8], gr < Nn ? 16 : 0);
    }
    {
        const __half* Wz = Wbase + (size_t)slots[0] * (Dd * Dd);
#pragma unroll
        for (int it = 0; it < 8; it++) {
            int idx = tid + it * 256;
            int n = idx >> 4, c8 = (idx & 15) * 8;
            cp16(&Bs[n][c8], &Wz[(size_t)n * 128 + c8], 16);
        }
    }
    asm volatile("cp.async.commit_group;");

    // ldmatrix base addresses (fixed across slots)
    int l7 = lane & 7, lm = (lane >> 3) & 1, lh = lane >> 4;
    uint32_t aAddr[2], bAddr[4];
#pragma unroll
    for (int mt = 0; mt < 2; mt++)
        aAddr[mt] = sma(&As[wm + mt * 16 + lm * 8 + l7][lh * 8]);
#pragma unroll
    for (int p = 0; p < 4; p++)
        bAddr[p] = sma(&Bs[wn + (2 * p + lh) * 8 + l7][lm * 8]);

    for (int si = 0; si < ns; si++) {
        int r = slots[si];

        float acc[2][8][4];
#pragma unroll
        for (int mt = 0; mt < 2; mt++)
#pragma unroll
            for (int nt = 0; nt < 8; nt++)
#pragma unroll
                for (int q = 0; q < 4; q++) acc[mt][nt][q] = 0.f;

        asm volatile("cp.async.wait_group 0;" ::: "memory");
        __syncthreads();

#pragma unroll
        for (int ks = 0; ks < 8; ks++) {
            uint32_t off = ks * 32;
            unsigned a0[4], a1[4];
            ldsm4(a0[0], a0[1], a0[2], a0[3], aAddr[0] + off);
            ldsm4(a1[0], a1[1], a1[2], a1[3], aAddr[1] + off);
#pragma unroll
            for (int p = 0; p < 4; p++) {
                unsigned b0, b1, b2, b3;
                ldsm4(b0, b1, b2, b3, bAddr[p] + off);
                mma_f16(acc[0][2 * p + 0], a0[0], a0[1], a0[2], a0[3], b0, b1);
                mma_f16(acc[0][2 * p + 1], a0[0], a0[1], a0[2], a0[3], b2, b3);
                mma_f16(acc[1][2 * p + 0], a1[0], a1[1], a1[2], a1[3], b0, b1);
                mma_f16(acc[1][2 * p + 1], a1[0], a1[1], a1[2], a1[3], b2, b3);
            }
        }
        __syncthreads();   // all warps done reading Bs

        // prefetch next slot's B — overlaps the epilogue below (Ch is separate)
        if (si + 1 < ns) {
            const __half* Wn = Wbase + (size_t)slots[si + 1] * (Dd * Dd);
#pragma unroll
            for (int it = 0; it < 8; it++) {
                int idx = tid + it * 256;
                int n = idx >> 4, c8 = (idx & 15) * 8;
                cp16(&Bs[n][c8], &Wn[(size_t)n * 128 + c8], 16);
            }
            asm volatile("cp.async.commit_group;");
        }

        if (r == Rr) {
            // root: acc + bias red.add into g_acc
#pragma unroll
            for (int mt = 0; mt < 2; mt++)
#pragma unroll
                for (int h = 0; h < 2; h++) {
                    int row = row0 + wm + mt * 16 + (lane >> 2) + h * 8;
                    if (row >= Nn) continue;
                    float* outr = g_acc + (size_t)row * 128;
#pragma unroll
                    for (int nt = 0; nt < 8; nt++) {
                        int col = wn + nt * 8 + 2 * (lane & 3);
                        float v0 = acc[mt][nt][h * 2 + 0] + bias[col];
                        float v1 = acc[mt][nt][h * 2 + 1] + bias[col + 1];
                        asm volatile("red.global.add.v2.f32 [%0], {%1,%2};"
                                     :: "l"(outr + col), "f"(v0), "f"(v1) : "memory");
                    }
                }
            continue;   // root is last; loop ends
        }

        // two-phase epilogue: stage 64 rows into Ch, scatter that half's bucket
        int bkt0 = r * NG + tile * 2;
#pragma unroll
        for (int h2 = 0; h2 < 2; h2++) {
            if ((wm < 64) == (h2 == 0)) {
                int rbase = wm - h2 * 64;
#pragma unroll
                for (int mt = 0; mt < 2; mt++)
#pragma unroll
                    for (int h = 0; h < 2; h++) {
                        int rl = rbase + mt * 16 + h * 8 + (lane >> 2);
#pragma unroll
                        for (int nt = 0; nt < 8; nt++) {
                            int col = wn + nt * 8 + 2 * (lane & 3);
                            *(float2*)&Ch[rl][col] =
                                make_float2(acc[mt][nt][h * 2 + 0], acc[mt][nt][h * 2 + 1]);
                        }
                    }
            }
            __syncthreads();

            int bkt = bkt0 + h2;
            int lo = g_boff[bkt], hi = g_boff[bkt + 1];
            int i = lo + wid;
            int nsrc = 0, ndst = 0;
            float nw = 0.f;
            if (i < hi) { nsrc = g_bsrc[i]; ndst = g_bdst[i]; nw = g_bw[i]; }
            while (i < hi) {
                int sloc = nsrc & 63;
                int dst  = ndst;
                float w  = nw;
                int inext = i + 8;
                if (inext < hi) { nsrc = g_bsrc[inext]; ndst = g_bdst[inext]; nw = g_bw[inext]; }
                float4 v = *(const float4*)&Ch[sloc][lane * 4];
                v.x *= w; v.y *= w; v.z *= w; v.w *= w;
                float* p = g_acc + (size_t)dst * 128 + lane * 4;
                asm volatile("red.global.add.v4.f32 [%0], {%1,%2,%3,%4};"
                             :: "l"(p), "f"(v.x), "f"(v.y), "f"(v.z), "f"(v.w) : "memory");
                i = inext;
            }
            __syncthreads();
        }
    }
}

// ---------------- launch ----------------
extern "C" void kernel_launch(void* const* d_in, const int* in_sizes, int n_in,
                              void* d_out, int out_size) {
    const int*   edge_index   = (const int*)d_in[0];
    const int*   edge_type    = (const int*)d_in[1];
    const int*   node_indices = (const int*)d_in[2];
    const float* file_feats   = (const float*)d_in[3];
    const int*   file_idx     = (const int*)d_in[4];
    const float* domain_feats = (const float*)d_in[5];
    const int*   domain_idx   = (const int*)d_in[6];
    const float* ip_feats     = (const float*)d_in[7];
    const int*   ip_idx       = (const int*)d_in[8];
    const float* fallback     = (const float*)d_in[9];
    const float* Wf  = (const float*)d_in[10];
    const float* bf  = (const float*)d_in[11];
    const float* Wd  = (const float*)d_in[12];
    const float* bd  = (const float*)d_in[13];
    const float* Wi  = (const float*)d_in[14];
    const float* bi  = (const float*)d_in[15];
    const float* comp1  = (const float*)d_in[16];
    const float* bases1 = (const float*)d_in[17];
    const float* root1  = (const float*)d_in[18];
    const float* bias1  = (const float*)d_in[19];
    const float* comp2  = (const float*)d_in[20];
    const float* bases2 = (const float*)d_in[21];
    const float* root2  = (const float*)d_in[22];
    const float* bias2  = (const float*)d_in[23];
    const float* ln1_g  = (const float*)d_in[24];
    const float* ln1_b  = (const float*)d_in[25];
    const float* ln2_g  = (const float*)d_in[26];
    const float* ln2_b  = (const float*)d_in[27];
    const float* Wc1 = (const float*)d_in[28];
    const float* bc1 = (const float*)d_in[29];
    const float* Wc2 = (const float*)d_in[30];
    const float* bc2 = (const float*)d_in[31];
    float* out = (float*)d_out;

    static int smem_set = 0;
    if (!smem_set) {
        cudaFuncSetAttribute(ftg_h, cudaFuncAttributeMaxDynamicSharedMemorySize, SMH_TOTAL);
        smem_set = 1;
    }

    // ---- zero counters, then fused proj || copy/acc-zero || count ----
    k_zero<<<(Rr * Nn + 255) / 256, 256>>>();
    k_mega<<<NB_PROJ + NB_COPY + NB_CNT, 256>>>(
        file_feats,   Wf, bf, file_idx,   20000, 256,
        domain_feats, Wd, bd, domain_idx, 15000, 128,
        ip_feats,     Wi, bi, ip_idx,     10000, 64,
        fallback, edge_index, edge_type);

    // ---- both layers' W + bucket scan (fused) ----
    k_setup<<<dim3(NB_BW + 1, 2), 1024>>>(comp1, bases1, root1, comp2, bases2, root2);

    // ---- place edges ----
    k_place<<<(Ee + 255) / 256, 256>>>(edge_index, edge_type);

    // ---- layer 1 ----
    ftg_h<<<NTILE, 256, SMH_TOTAL>>>(bias1, 0);
    k_ln<<<(Nn * 32 + 255) / 256, 256>>>(ln1_g, ln1_b, 1);

    // ---- layer 2 ----
    ftg_h<<<NTILE, 256, SMH_TOTAL>>>(bias2, 1);
    k_ln<<<(Nn * 32 + 255) / 256, 256>>>(ln2_g, ln2_b, 0);

    // ---- classifier ----
    cgemm<<<NSEL / 128, 256>>>(node_indices, Wc1, bc1);
    k_final<<<(NSEL * NCc + 255) / 256, 256>>>(Wc2, bc2, out);
}

// round 14
// speedup vs baseline: 1.3234x; 1.3234x over previous
#include <cuda_runtime.h>
#include <cuda_fp16.h>
#include <cstdint>

// Problem constants
#define Nn    50000
#define Dd    128
#define Rr    10
#define Ee    800000
#define NSEL  8192
#define NCc   12
#define NTILE 391                 // ceil(Nn/128)
#define NG    782                 // ceil(Nn/64) src groups
#define NBKT  (Rr * NG)
#define SLOTS (Rr + 1)            // 10 relations + root

// ftg_h smem: A half[128][136] + B half[128][136]; Ch f32[128][132] overlays A+B
#define SMH_A_BYTES (128 * 136 * 2)     // 34816
#define SMH_TOTAL   (2 * SMH_A_BYTES)   // 69632  (Ch needs 67584 <= this)
#define CH_STRIDE   132

// mega-kernel block ranges
#define NB_PROJ  354      // 157 + 118 + 79
#define NB_COPY  6250     // Nn*Dd/4 / 256
#define NB_CNT   3125     // Ee / 256

// k_setup: build-W blocks (1024 thr) + 1 scan block
#define NB_BW    176      // SLOTS*Dd*Dd / 1024

// ---------------- device scratch ----------------
__device__ __half g_xh[Nn * Dd];              // node features, fp16
__device__ float  g_acc[Nn * Dd];             // conv accumulator (fp32)
__device__ __half g_Wh[2 * SLOTS * Dd * Dd];  // both layers' W^T [layer][slot][n][k]
__device__ int    g_icnt[Rr * Nn];
__device__ float  g_hsel[NSEL * Dd];
__device__ int    g_bcnt[NBKT];
__device__ int    g_bcur[NBKT];
__device__ int    g_boff[NBKT + 1];
__device__ int    g_bsrc[Ee];
__device__ int    g_bdst[Ee];
__device__ float  g_bw[Ee];

// ---------------- helpers ----------------
__device__ __forceinline__ unsigned f2tf(float f) {
    unsigned u;
    asm("cvt.rna.tf32.f32 %0, %1;" : "=r"(u) : "f"(f));
    return u;
}

__device__ __forceinline__ void mma_tf32(float c[4], const unsigned a[4], const unsigned b[2]) {
    asm volatile("mma.sync.aligned.m16n8k8.row.col.f32.tf32.tf32.f32 "
                 "{%0,%1,%2,%3}, {%4,%5,%6,%7}, {%8,%9}, {%0,%1,%2,%3};"
                 : "+f"(c[0]), "+f"(c[1]), "+f"(c[2]), "+f"(c[3])
                 : "r"(a[0]), "r"(a[1]), "r"(a[2]), "r"(a[3]), "r"(b[0]), "r"(b[1]));
}

__device__ __forceinline__ void mma_f16(float c[4], unsigned a0, unsigned a1,
                                        unsigned a2, unsigned a3,
                                        unsigned b0, unsigned b1) {
    asm volatile("mma.sync.aligned.m16n8k16.row.col.f32.f16.f16.f32 "
                 "{%0,%1,%2,%3}, {%4,%5,%6,%7}, {%8,%9}, {%0,%1,%2,%3};"
                 : "+f"(c[0]), "+f"(c[1]), "+f"(c[2]), "+f"(c[3])
                 : "r"(a0), "r"(a1), "r"(a2), "r"(a3), "r"(b0), "r"(b1));
}

__device__ __forceinline__ void cp16(void* smem, const void* g, int srcsize) {
    unsigned a = (unsigned)__cvta_generic_to_shared(smem);
    asm volatile("cp.async.ca.shared.global [%0], [%1], 16, %2;"
                 :: "r"(a), "l"(g), "r"(srcsize));
}

__device__ __forceinline__ void ldsm4(unsigned& r0, unsigned& r1, unsigned& r2, unsigned& r3,
                                      uint32_t addr) {
    asm volatile("ldmatrix.sync.aligned.m8n8.x4.shared.b16 {%0,%1,%2,%3}, [%4];"
                 : "=r"(r0), "=r"(r1), "=r"(r2), "=r"(r3) : "r"(addr));
}

__device__ __forceinline__ uint32_t sma(const void* p) {
    return (uint32_t)__cvta_generic_to_shared(p);
}

// ---------------- small kernels ----------------
__global__ void k_zero() {
    int i = blockIdx.x * blockDim.x + threadIdx.x;
    if (i < Rr * Nn) g_icnt[i] = 0;
    if (i < NBKT) { g_bcnt[i] = 0; g_bcur[i] = 0; }
}

// fused: builds both layers' W^T (fp16) AND runs the bucket scan in the last block.
// grid = (NB_BW + 1, 2), block = 1024.
__global__ void k_setup(const float* __restrict__ comp1, const float* __restrict__ bases1,
                        const float* __restrict__ root1,
                        const float* __restrict__ comp2, const float* __restrict__ bases2,
                        const float* __restrict__ root2) {
    int t = threadIdx.x;
    if (blockIdx.x == NB_BW) {
        if (blockIdx.y != 0) return;
        // ---- warp-shuffle two-level scan over NBKT bucket counts -> g_boff ----
        __shared__ int wsum[32];
        int lane = t & 31, wid = t >> 5;
        int cnt[8];
        int s = 0;
#pragma unroll
        for (int j = 0; j < 8; j++) {
            int b = t * 8 + j;
            cnt[j] = (b < NBKT) ? g_bcnt[b] : 0;
            s += cnt[j];
        }
        int incl = s;
#pragma unroll
        for (int o = 1; o < 32; o <<= 1) {
            int v = __shfl_up_sync(0xffffffffu, incl, o);
            if (lane >= o) incl += v;
        }
        if (lane == 31) wsum[wid] = incl;
        __syncthreads();
        if (wid == 0) {
            int v = wsum[lane];
            int iv = v;
#pragma unroll
            for (int o = 1; o < 32; o <<= 1) {
                int u = __shfl_up_sync(0xffffffffu, iv, o);
                if (lane >= o) iv += u;
            }
            wsum[lane] = iv - v;
            if (lane == 31) g_boff[NBKT] = iv;
        }
        __syncthreads();
        int run = wsum[wid] + (incl - s);
#pragma unroll
        for (int j = 0; j < 8; j++) {
            int b = t * 8 + j;
            if (b < NBKT) { g_boff[b] = run; run += cnt[j]; }
        }
        return;
    }
    // ---- build W element ----
    int i = blockIdx.x * 1024 + t;
    int layer = blockIdx.y;
    const float* comp  = layer ? comp2  : comp1;
    const float* bases = layer ? bases2 : bases1;
    const float* root  = layer ? root2  : root1;
    int slot = i >> 14;
    int idx  = i & 16383;          // n*128 + k
    int n = idx >> 7, k = idx & 127;
    int src = k * 128 + n;
    float v;
    if (slot < Rr) {
        v = 0.f;
#pragma unroll
        for (int b = 0; b < 4; b++)
            v += comp[slot * 4 + b] * bases[b * Dd * Dd + src];
    } else {
        v = root[src];
    }
    g_Wh[layer * SLOTS * Dd * Dd + i] = __float2half_rn(v);
}

// places edges AND computes the mean weight inline
__global__ void k_place(const int* __restrict__ ei, const int* __restrict__ et) {
    int e = blockIdx.x * blockDim.x + threadIdx.x;
    if (e >= Ee) return;
    int r = et[e];
    int s = ei[e], t = ei[Ee + e];
    int key = r * NG + (s >> 6);
    int pos = g_boff[key] + atomicAdd(&g_bcur[key], 1);
    g_bsrc[pos] = s;
    g_bdst[pos] = t;
    g_bw[pos]   = 1.0f / fmaxf((float)g_icnt[r * Nn + t], 1.0f);
}

// one warp per node: LayerNorm (+optional ReLU) -> g_xh (fp16); zeroes acc
__global__ void k_ln(const float* __restrict__ g, const float* __restrict__ b, int relu) {
    int gt = blockIdx.x * blockDim.x + threadIdx.x;
    int node = gt >> 5;
    if (node >= Nn) return;
    int lane = gt & 31;
    float4 v = ((const float4*)g_acc)[node * 32 + lane];
    float s = v.x + v.y + v.z + v.w;
    float q = v.x * v.x + v.y * v.y + v.z * v.z + v.w * v.w;
#pragma unroll
    for (int o = 16; o; o >>= 1) {
        s += __shfl_xor_sync(0xffffffffu, s, o);
        q += __shfl_xor_sync(0xffffffffu, q, o);
    }
    float mean = s * (1.f / 128.f);
    float var  = q * (1.f / 128.f) - mean * mean;
    float rstd = rsqrtf(var + 1e-5f);
    float4 gg = ((const float4*)g)[lane];
    float4 bb = ((const float4*)b)[lane];
    float4 o4;
    o4.x = (v.x - mean) * rstd * gg.x + bb.x;
    o4.y = (v.y - mean) * rstd * gg.y + bb.y;
    o4.z = (v.z - mean) * rstd * gg.z + bb.z;
    o4.w = (v.w - mean) * rstd * gg.w + bb.w;
    if (relu) {
        o4.x = fmaxf(o4.x, 0.f); o4.y = fmaxf(o4.y, 0.f);
        o4.z = fmaxf(o4.z, 0.f); o4.w = fmaxf(o4.w, 0.f);
    }
    __half2 p0 = __halves2half2(__float2half_rn(o4.x), __float2half_rn(o4.y));
    __half2 p1 = __halves2half2(__float2half_rn(o4.z), __float2half_rn(o4.w));
    ((uint2*)g_xh)[node * 32 + lane] = make_uint2(*(unsigned*)&p0, *(unsigned*)&p1);
    ((float4*)g_acc)[node * 32 + lane] = make_float4(0.f, 0.f, 0.f, 0.f);
}

__global__ void k_final(const float* __restrict__ W, const float* __restrict__ b,
                        float* __restrict__ out) {
    int gt = blockIdx.x * blockDim.x + threadIdx.x;
    if (gt >= NSEL * NCc) return;
    int i = gt / NCc, c = gt % NCc;
    const float* hr = g_hsel + i * Dd;
    float s = b[c];
#pragma unroll 8
    for (int k = 0; k < Dd; k++) s += hr[k] * W[k * NCc + c];
    out[gt] = s;
}

// ---------------- mega kernel: proj (3 segs) || fallback-copy+acc-zero || edge-count --
__global__ void __launch_bounds__(256)
k_mega(const float* A0, const float* W0, const float* b0, const int* x0, int M0, int K0,
       const float* A1, const float* W1, const float* b1, const int* x1, int M1, int K1,
       const float* A2, const float* W2, const float* b2, const int* x2, int M2, int K2,
       const float* __restrict__ fallback,
       const int* __restrict__ ei, const int* __restrict__ et) {
    int blk = blockIdx.x;
    int tid = threadIdx.x;

    if (blk >= NB_PROJ) {
        if (blk < NB_PROJ + NB_COPY) {
            int i = (blk - NB_PROJ) * 256 + tid;
            if (i < Nn * Dd / 4) {
                if (i >= 45000 * 32) {
                    float4 v = ((const float4*)fallback)[i];
                    __half2 p0 = __halves2half2(__float2half_rn(v.x), __float2half_rn(v.y));
                    __half2 p1 = __halves2half2(__float2half_rn(v.z), __float2half_rn(v.w));
                    ((uint2*)g_xh)[i] = make_uint2(*(unsigned*)&p0, *(unsigned*)&p1);
                }
                ((float4*)g_acc)[i] = make_float4(0.f, 0.f, 0.f, 0.f);
            }
        } else {
            int e = (blk - NB_PROJ - NB_COPY) * 256 + tid;
            if (e < Ee) {
                int r = et[e];
                atomicAdd(&g_icnt[r * Nn + ei[Ee + e]], 1);
                atomicAdd(&g_bcnt[r * NG + (ei[e] >> 6)], 1);
            }
        }
        return;
    }

    // ---- projection GEMM segment ----
    const float *A, *B, *bias;
    const int* rowIdx;
    int M, K, row0;
    if (blk < 157)      { A = A0; B = W0; bias = b0; rowIdx = x0; M = M0; K = K0; row0 = blk * 128; }
    else if (blk < 275) { A = A1; B = W1; bias = b1; rowIdx = x1; M = M1; K = K1; row0 = (blk - 157) * 128; }
    else                { A = A2; B = W2; bias = b2; rowIdx = x2; M = M2; K = K2; row0 = (blk - 275) * 128; }

    __shared__ unsigned As[128][36];
    __shared__ unsigned Bs[32][136];
    float acc[2][8][4];
#pragma unroll
    for (int mt = 0; mt < 2; mt++)
#pragma unroll
        for (int nt = 0; nt < 8; nt++)
#pragma unroll
            for (int q = 0; q < 4; q++) acc[mt][nt][q] = 0.f;

    int lane = tid & 31, wid = tid >> 5;
    int wm = (wid >> 1) * 32;
    int wn = (wid & 1) * 64;

    for (int kb = 0; kb < K; kb += 32) {
#pragma unroll
        for (int it = 0; it < 4; it++) {
            int idx = tid + it * 256;
            int m = idx >> 3;
            int kq = (idx & 7) * 4;
            float4 v = make_float4(0.f, 0.f, 0.f, 0.f);
            int row = row0 + m;
            if (row < M) v = *(const float4*)&A[(size_t)row * K + kb + kq];
            As[m][kq + 0] = f2tf(v.x); As[m][kq + 1] = f2tf(v.y);
            As[m][kq + 2] = f2tf(v.z); As[m][kq + 3] = f2tf(v.w);
        }
#pragma unroll
        for (int it = 0; it < 4; it++) {
            int idx = tid + it * 256;
            int k = idx >> 5;
            int nq = (idx & 31) * 4;
            float4 v = *(const float4*)&B[(size_t)(kb + k) * 128 + nq];
            Bs[k][nq + 0] = f2tf(v.x); Bs[k][nq + 1] = f2tf(v.y);
            Bs[k][nq + 2] = f2tf(v.z); Bs[k][nq + 3] = f2tf(v.w);
        }
        __syncthreads();
#pragma unroll
        for (int ks = 0; ks < 4; ks++) {
            int k0 = ks * 8;
            unsigned af[2][4];
#pragma unroll
            for (int mt = 0; mt < 2; mt++) {
                int r = wm + mt * 16 + (lane >> 2);
                int c = k0 + (lane & 3);
                af[mt][0] = As[r][c];     af[mt][1] = As[r + 8][c];
                af[mt][2] = As[r][c + 4]; af[mt][3] = As[r + 8][c + 4];
            }
#pragma unroll
            for (int nt = 0; nt < 8; nt++) {
                unsigned bf[2];
                int br = k0 + (lane & 3);
                int bc = wn + nt * 8 + (lane >> 2);
                bf[0] = Bs[br][bc];
                bf[1] = Bs[br + 4][bc];
                mma_tf32(acc[0][nt], af[0], bf);
                mma_tf32(acc[1][nt], af[1], bf);
            }
        }
        __syncthreads();
    }

#pragma unroll
    for (int mt = 0; mt < 2; mt++) {
#pragma unroll
        for (int h = 0; h < 2; h++) {
            int row = row0 + wm + mt * 16 + (lane >> 2) + h * 8;
            if (row >= M) continue;
            int cr = rowIdx[row];
#pragma unroll
            for (int nt = 0; nt < 8; nt++) {
                int col = wn + nt * 8 + 2 * (lane & 3);
                float v0 = acc[mt][nt][h * 2 + 0] + bias[col];
                float v1 = acc[mt][nt][h * 2 + 1] + bias[col + 1];
                __half2 p = __halves2half2(__float2half_rn(v0), __float2half_rn(v1));
                *(unsigned*)&g_xh[(size_t)cr * 128 + col] = *(unsigned*)&p;
            }
        }
    }
}

// ---------------- classifier GEMM: half input (exact cvt), tf32 math, f32 out ----
__global__ void __launch_bounds__(256)
cgemm(const int* __restrict__ aIdx, const float* __restrict__ B,
      const float* __restrict__ bias) {
    int row0 = blockIdx.x * 128;
    __shared__ unsigned As[128][36];
    __shared__ unsigned Bs[32][136];
    float acc[2][8][4];
#pragma unroll
    for (int mt = 0; mt < 2; mt++)
#pragma unroll
        for (int nt = 0; nt < 8; nt++)
#pragma unroll
            for (int q = 0; q < 4; q++) acc[mt][nt][q] = 0.f;

    int tid = threadIdx.x;
    int lane = tid & 31, wid = tid >> 5;
    int wm = (wid >> 1) * 32;
    int wn = (wid & 1) * 64;

    for (int kb = 0; kb < 128; kb += 32) {
#pragma unroll
        for (int it = 0; it < 4; it++) {
            int idx = tid + it * 256;
            int m = idx >> 3;
            int kq = (idx & 7) * 4;
            int row = row0 + m;
            int ar = aIdx[row];
            const __half* src = &g_xh[(size_t)ar * 128 + kb + kq];
            As[m][kq + 0] = f2tf(__half2float(src[0]));
            As[m][kq + 1] = f2tf(__half2float(src[1]));
            As[m][kq + 2] = f2tf(__half2float(src[2]));
            As[m][kq + 3] = f2tf(__half2float(src[3]));
        }
#pragma unroll
        for (int it = 0; it < 4; it++) {
            int idx = tid + it * 256;
            int k = idx >> 5;
            int nq = (idx & 31) * 4;
            float4 v = *(const float4*)&B[(size_t)(kb + k) * 128 + nq];
            Bs[k][nq + 0] = f2tf(v.x); Bs[k][nq + 1] = f2tf(v.y);
            Bs[k][nq + 2] = f2tf(v.z); Bs[k][nq + 3] = f2tf(v.w);
        }
        __syncthreads();
#pragma unroll
        for (int ks = 0; ks < 4; ks++) {
            int k0 = ks * 8;
            unsigned af[2][4];
#pragma unroll
            for (int mt = 0; mt < 2; mt++) {
                int r = wm + mt * 16 + (lane >> 2);
                int c = k0 + (lane & 3);
                af[mt][0] = As[r][c];     af[mt][1] = As[r + 8][c];
                af[mt][2] = As[r][c + 4]; af[mt][3] = As[r + 8][c + 4];
            }
#pragma unroll
            for (int nt = 0; nt < 8; nt++) {
                unsigned bf[2];
                int br = k0 + (lane & 3);
                int bc = wn + nt * 8 + (lane >> 2);
                bf[0] = Bs[br][bc];
                bf[1] = Bs[br + 4][bc];
                mma_tf32(acc[0][nt], af[0], bf);
                mma_tf32(acc[1][nt], af[1], bf);
            }
        }
        __syncthreads();
    }

#pragma unroll
    for (int mt = 0; mt < 2; mt++) {
#pragma unroll
        for (int h = 0; h < 2; h++) {
            int row = row0 + wm + mt * 16 + (lane >> 2) + h * 8;
#pragma unroll
            for (int nt = 0; nt < 8; nt++) {
                int col = wn + nt * 8 + 2 * (lane & 3);
                float v0 = fmaxf(acc[mt][nt][h * 2 + 0] + bias[col], 0.f);
                float v1 = fmaxf(acc[mt][nt][h * 2 + 1] + bias[col + 1], 0.f);
                *(float2*)&g_hsel[(size_t)row * 128 + col] = make_float2(v0, v1);
            }
        }
    }
}

// ---------------- fp16 fused dense GEMM + edge scatter (single-phase epilogue) ------
// grid = (NTILE, SLOTS) — 4301 independent blocks: cross-block MMA/scatter overlap.
__global__ void __launch_bounds__(256, 2)
ftg_h(const float* __restrict__ bias, int layer) {
    extern __shared__ __align__(16) char dsm[];
    __half (*As)[136] = (__half(*)[136])dsm;
    __half (*Bs)[136] = (__half(*)[136])(dsm + SMH_A_BYTES);
    float  (*Ch)[CH_STRIDE] = (float(*)[CH_STRIDE])dsm;   // overlays A+B after MMA

    int tile = blockIdx.x;
    int r    = blockIdx.y;
    int row0 = tile * 128;
    bool isRoot = (r == Rr);

    int bkt0 = 0;
    if (!isRoot) {
        bkt0 = r * NG + tile * 2;
        if (g_boff[bkt0] == g_boff[bkt0 + 2]) return;
    }

    int tid = threadIdx.x;
    int lane = tid & 31, wid = tid >> 5;
    int wm = (wid >> 1) * 32;
    int wn = (wid & 1) * 64;

    const __half* Wz = g_Wh + (size_t)(layer * SLOTS + r) * (Dd * Dd);

#pragma unroll
    for (int it = 0; it < 8; it++) {
        int idx = tid + it * 256;
        int m = idx >> 4, c8 = (idx & 15) * 8;
        int gr = row0 + m;
        cp16(&As[m][c8], &g_xh[(size_t)gr * 128 + c8], gr < Nn ? 16 : 0);
    }
#pragma unroll
    for (int it = 0; it < 8; it++) {
        int idx = tid + it * 256;
        int n = idx >> 4, c8 = (idx & 15) * 8;
        cp16(&Bs[n][c8], &Wz[(size_t)n * 128 + c8], 16);
    }
    asm volatile("cp.async.commit_group;");

    float acc[2][8][4];
#pragma unroll
    for (int mt = 0; mt < 2; mt++)
#pragma unroll
        for (int nt = 0; nt < 8; nt++)
#pragma unroll
            for (int q = 0; q < 4; q++) acc[mt][nt][q] = 0.f;

    // ldmatrix base addresses
    int l7 = lane & 7, lm = (lane >> 3) & 1, lh = lane >> 4;
    uint32_t aAddr[2], bAddr[4];
#pragma unroll
    for (int mt = 0; mt < 2; mt++)
        aAddr[mt] = sma(&As[wm + mt * 16 + lm * 8 + l7][lh * 8]);
#pragma unroll
    for (int p = 0; p < 4; p++)
        bAddr[p] = sma(&Bs[wn + (2 * p + lh) * 8 + l7][lm * 8]);

    asm volatile("cp.async.wait_group 0;" ::: "memory");
    __syncthreads();

#pragma unroll
    for (int ks = 0; ks < 8; ks++) {
        uint32_t off = ks * 32;
        unsigned a0[4], a1[4];
        ldsm4(a0[0], a0[1], a0[2], a0[3], aAddr[0] + off);
        ldsm4(a1[0], a1[1], a1[2], a1[3], aAddr[1] + off);
#pragma unroll
        for (int p = 0; p < 4; p++) {
            unsigned b0, b1, b2, b3;
            ldsm4(b0, b1, b2, b3, bAddr[p] + off);
            mma_f16(acc[0][2 * p + 0], a0[0], a0[1], a0[2], a0[3], b0, b1);
            mma_f16(acc[0][2 * p + 1], a0[0], a0[1], a0[2], a0[3], b2, b3);
            mma_f16(acc[1][2 * p + 0], a1[0], a1[1], a1[2], a1[3], b0, b1);
            mma_f16(acc[1][2 * p + 1], a1[0], a1[1], a1[2], a1[3], b2, b3);
        }
    }

    if (isRoot) {
#pragma unroll
        for (int mt = 0; mt < 2; mt++)
#pragma unroll
            for (int h = 0; h < 2; h++) {
                int row = row0 + wm + mt * 16 + (lane >> 2) + h * 8;
                if (row >= Nn) continue;
                float* outr = g_acc + (size_t)row * 128;
#pragma unroll
                for (int nt = 0; nt < 8; nt++) {
                    int col = wn + nt * 8 + 2 * (lane & 3);
                    float v0 = acc[mt][nt][h * 2 + 0] + bias[col];
                    float v1 = acc[mt][nt][h * 2 + 1] + bias[col + 1];
                    asm volatile("red.global.add.v2.f32 [%0], {%1,%2};"
                                 :: "l"(outr + col), "f"(v0), "f"(v1) : "memory");
                }
            }
        return;
    }

    __syncthreads();   // all warps done with A/B smem (ldmatrix) before Ch overlay

    // stage full 128-row tile into Ch (all 8 warps write their own acc rows)
#pragma unroll
    for (int mt = 0; mt < 2; mt++)
#pragma unroll
        for (int h = 0; h < 2; h++) {
            int rl = wm + mt * 16 + h * 8 + (lane >> 2);
#pragma unroll
            for (int nt = 0; nt < 8; nt++) {
                int col = wn + nt * 8 + 2 * (lane & 3);
                *(float2*)&Ch[rl][col] =
                    make_float2(acc[mt][nt][h * 2 + 0], acc[mt][nt][h * 2 + 1]);
            }
        }
    __syncthreads();

    // single scatter loop over the contiguous bucket pair (pipelined)
    int lo = g_boff[bkt0], hi = g_boff[bkt0 + 2];
    int i = lo + wid;
    int nsrc = 0, ndst = 0;
    float nw = 0.f;
    if (i < hi) { nsrc = g_bsrc[i]; ndst = g_bdst[i]; nw = g_bw[i]; }
    while (i < hi) {
        int sloc = nsrc & 127;
        int dst  = ndst;
        float w  = nw;
        int inext = i + 8;
        if (inext < hi) { nsrc = g_bsrc[inext]; ndst = g_bdst[inext]; nw = g_bw[inext]; }
        float4 v = *(const float4*)&Ch[sloc][lane * 4];
        v.x *= w; v.y *= w; v.z *= w; v.w *= w;
        float* p = g_acc + (size_t)dst * 128 + lane * 4;
        asm volatile("red.global.add.v4.f32 [%0], {%1,%2,%3,%4};"
                     :: "l"(p), "f"(v.x), "f"(v.y), "f"(v.z), "f"(v.w) : "memory");
        i = inext;
    }
}

// ---------------- launch ----------------
extern "C" void kernel_launch(void* const* d_in, const int* in_sizes, int n_in,
                              void* d_out, int out_size) {
    const int*   edge_index   = (const int*)d_in[0];
    const int*   edge_type    = (const int*)d_in[1];
    const int*   node_indices = (const int*)d_in[2];
    const float* file_feats   = (const float*)d_in[3];
    const int*   file_idx     = (const int*)d_in[4];
    const float* domain_feats = (const float*)d_in[5];
    const int*   domain_idx   = (const int*)d_in[6];
    const float* ip_feats     = (const float*)d_in[7];
    const int*   ip_idx       = (const int*)d_in[8];
    const float* fallback     = (const float*)d_in[9];
    const float* Wf  = (const float*)d_in[10];
    const float* bf  = (const float*)d_in[11];
    const float* Wd  = (const float*)d_in[12];
    const float* bd  = (const float*)d_in[13];
    const float* Wi  = (const float*)d_in[14];
    const float* bi  = (const float*)d_in[15];
    const float* comp1  = (const float*)d_in[16];
    const float* bases1 = (const float*)d_in[17];
    const float* root1  = (const float*)d_in[18];
    const float* bias1  = (const float*)d_in[19];
    const float* comp2  = (const float*)d_in[20];
    const float* bases2 = (const float*)d_in[21];
    const float* root2  = (const float*)d_in[22];
    const float* bias2  = (const float*)d_in[23];
    const float* ln1_g  = (const float*)d_in[24];
    const float* ln1_b  = (const float*)d_in[25];
    const float* ln2_g  = (const float*)d_in[26];
    const float* ln2_b  = (const float*)d_in[27];
    const float* Wc1 = (const float*)d_in[28];
    const float* bc1 = (const float*)d_in[29];
    const float* Wc2 = (const float*)d_in[30];
    const float* bc2 = (const float*)d_in[31];
    float* out = (float*)d_out;

    static int smem_set = 0;
    if (!smem_set) {
        cudaFuncSetAttribute(ftg_h, cudaFuncAttributeMaxDynamicSharedMemorySize, SMH_TOTAL);
        smem_set = 1;
    }

    // ---- zero counters, then fused proj || copy/acc-zero || count ----
    k_zero<<<(Rr * Nn + 255) / 256, 256>>>();
    k_mega<<<NB_PROJ + NB_COPY + NB_CNT, 256>>>(
        file_feats,   Wf, bf, file_idx,   20000, 256,
        domain_feats, Wd, bd, domain_idx, 15000, 128,
        ip_feats,     Wi, bi, ip_idx,     10000, 64,
        fallback, edge_index, edge_type);

    // ---- both layers' W + bucket scan (fused) ----
    k_setup<<<dim3(NB_BW + 1, 2), 1024>>>(comp1, bases1, root1, comp2, bases2, root2);

    // ---- place edges ----
    k_place<<<(Ee + 255) / 256, 256>>>(edge_index, edge_type);

    dim3 fgrid(NTILE, SLOTS);

    // ---- layer 1 ----
    ftg_h<<<fgrid, 256, SMH_TOTAL>>>(bias1, 0);
    k_ln<<<(Nn * 32 + 255) / 256, 256>>>(ln1_g, ln1_b, 1);

    // ---- layer 2 ----
    ftg_h<<<fgrid, 256, SMH_TOTAL>>>(bias2, 1);
    k_ln<<<(Nn * 32 + 255) / 256, 256>>>(ln2_g, ln2_b, 0);

    // ---- classifier ----
    cgemm<<<NSEL / 128, 256>>>(node_indices, Wc1, bc1);
    k_final<<<(NSEL * NCc + 255) / 256, 256>>>(Wc2, bc2, out);
}

// round 15
// speedup vs baseline: 1.3486x; 1.0191x over previous
#include <cuda_runtime.h>
#include <cuda_fp16.h>
#include <cstdint>

// Problem constants
#define Nn    50000
#define Dd    128
#define Rr    10
#define Ee    800000
#define NSEL  8192
#define NCc   12
#define NTILE 391                 // ceil(Nn/128)
#define NG    782                 // ceil(Nn/64) src groups
#define NBKT  (Rr * NG)
#define SLOTS (Rr + 1)            // 10 relations + root

// ftg_h smem: A half[128][136] + B half[128][136]; Ch f32[128][132] overlays A+B
#define SMH_A_BYTES (128 * 136 * 2)     // 34816
#define SMH_TOTAL   (2 * SMH_A_BYTES)   // 69632  (Ch needs 67584 <= this)
#define CH_STRIDE   132

// mega-kernel block ranges
#define NB_PROJ  354      // 157 + 118 + 79
#define NB_COPY  6250     // Nn*Dd/4 / 256
#define NB_CNT   3125     // Ee / 256

// k_setup: build-W blocks (1024 thr) + 1 scan block
#define NB_BW    176      // SLOTS*Dd*Dd / 1024

// ---------------- device scratch ----------------
__device__ __half g_xh[Nn * Dd];              // node features, fp16
__device__ float  g_acc[Nn * Dd];             // conv accumulator (fp32)
__device__ __half g_Wh[2 * SLOTS * Dd * Dd];  // both layers' W^T [layer][slot][n][k]
__device__ int    g_icnt[Rr * Nn];
__device__ float  g_hsel[NSEL * Dd];
__device__ int    g_bcnt[NBKT];
__device__ int    g_bcur[NBKT];
__device__ int    g_boff[NBKT + 1];
__device__ int2   g_bmeta[Ee];                // {sloc<<17|dst, f32bits(w)}

// ---------------- helpers ----------------
__device__ __forceinline__ unsigned f2tf(float f) {
    unsigned u;
    asm("cvt.rna.tf32.f32 %0, %1;" : "=r"(u) : "f"(f));
    return u;
}

__device__ __forceinline__ void mma_tf32(float c[4], const unsigned a[4], const unsigned b[2]) {
    asm volatile("mma.sync.aligned.m16n8k8.row.col.f32.tf32.tf32.f32 "
                 "{%0,%1,%2,%3}, {%4,%5,%6,%7}, {%8,%9}, {%0,%1,%2,%3};"
                 : "+f"(c[0]), "+f"(c[1]), "+f"(c[2]), "+f"(c[3])
                 : "r"(a[0]), "r"(a[1]), "r"(a[2]), "r"(a[3]), "r"(b[0]), "r"(b[1]));
}

__device__ __forceinline__ void mma_f16(float c[4], unsigned a0, unsigned a1,
                                        unsigned a2, unsigned a3,
                                        unsigned b0, unsigned b1) {
    asm volatile("mma.sync.aligned.m16n8k16.row.col.f32.f16.f16.f32 "
                 "{%0,%1,%2,%3}, {%4,%5,%6,%7}, {%8,%9}, {%0,%1,%2,%3};"
                 : "+f"(c[0]), "+f"(c[1]), "+f"(c[2]), "+f"(c[3])
                 : "r"(a0), "r"(a1), "r"(a2), "r"(a3), "r"(b0), "r"(b1));
}

__device__ __forceinline__ void cp16(void* smem, const void* g, int srcsize) {
    unsigned a = (unsigned)__cvta_generic_to_shared(smem);
    asm volatile("cp.async.ca.shared.global [%0], [%1], 16, %2;"
                 :: "r"(a), "l"(g), "r"(srcsize));
}

__device__ __forceinline__ void ldsm4(unsigned& r0, unsigned& r1, unsigned& r2, unsigned& r3,
                                      uint32_t addr) {
    asm volatile("ldmatrix.sync.aligned.m8n8.x4.shared.b16 {%0,%1,%2,%3}, [%4];"
                 : "=r"(r0), "=r"(r1), "=r"(r2), "=r"(r3) : "r"(addr));
}

__device__ __forceinline__ uint32_t sma(const void* p) {
    return (uint32_t)__cvta_generic_to_shared(p);
}

// ---------------- small kernels ----------------
__global__ void k_zero() {
    int i = blockIdx.x * blockDim.x + threadIdx.x;
    if (i < Rr * Nn) g_icnt[i] = 0;
    if (i < NBKT) { g_bcnt[i] = 0; g_bcur[i] = 0; }
}

// fused: builds both layers' W^T (fp16) AND runs the bucket scan in the last block.
__global__ void k_setup(const float* __restrict__ comp1, const float* __restrict__ bases1,
                        const float* __restrict__ root1,
                        const float* __restrict__ comp2, const float* __restrict__ bases2,
                        const float* __restrict__ root2) {
    int t = threadIdx.x;
    if (blockIdx.x == NB_BW) {
        if (blockIdx.y != 0) return;
        __shared__ int wsum[32];
        int lane = t & 31, wid = t >> 5;
        int cnt[8];
        int s = 0;
#pragma unroll
        for (int j = 0; j < 8; j++) {
            int b = t * 8 + j;
            cnt[j] = (b < NBKT) ? g_bcnt[b] : 0;
            s += cnt[j];
        }
        int incl = s;
#pragma unroll
        for (int o = 1; o < 32; o <<= 1) {
            int v = __shfl_up_sync(0xffffffffu, incl, o);
            if (lane >= o) incl += v;
        }
        if (lane == 31) wsum[wid] = incl;
        __syncthreads();
        if (wid == 0) {
            int v = wsum[lane];
            int iv = v;
#pragma unroll
            for (int o = 1; o < 32; o <<= 1) {
                int u = __shfl_up_sync(0xffffffffu, iv, o);
                if (lane >= o) iv += u;
            }
            wsum[lane] = iv - v;
            if (lane == 31) g_boff[NBKT] = iv;
        }
        __syncthreads();
        int run = wsum[wid] + (incl - s);
#pragma unroll
        for (int j = 0; j < 8; j++) {
            int b = t * 8 + j;
            if (b < NBKT) { g_boff[b] = run; run += cnt[j]; }
        }
        return;
    }
    int i = blockIdx.x * 1024 + t;
    int layer = blockIdx.y;
    const float* comp  = layer ? comp2  : comp1;
    const float* bases = layer ? bases2 : bases1;
    const float* root  = layer ? root2  : root1;
    int slot = i >> 14;
    int idx  = i & 16383;          // n*128 + k
    int n = idx >> 7, k = idx & 127;
    int src = k * 128 + n;
    float v;
    if (slot < Rr) {
        v = 0.f;
#pragma unroll
        for (int b = 0; b < 4; b++)
            v += comp[slot * 4 + b] * bases[b * Dd * Dd + src];
    } else {
        v = root[src];
    }
    g_Wh[layer * SLOTS * Dd * Dd + i] = __float2half_rn(v);
}

// places edges: one packed 8-byte store per edge (sloc|dst, weight)
__global__ void k_place(const int* __restrict__ ei, const int* __restrict__ et) {
    int e = blockIdx.x * blockDim.x + threadIdx.x;
    if (e >= Ee) return;
    int r = et[e];
    int s = ei[e], t = ei[Ee + e];
    int key = r * NG + (s >> 6);
    int pos = g_boff[key] + atomicAdd(&g_bcur[key], 1);
    float w = 1.0f / fmaxf((float)g_icnt[r * Nn + t], 1.0f);
    g_bmeta[pos] = make_int2(((s & 127) << 17) | t, __float_as_int(w));
}

// one warp per node: LayerNorm (+optional ReLU) -> g_xh (fp16); optionally zeroes acc
__global__ void k_ln(const float* __restrict__ g, const float* __restrict__ b,
                     int relu, int zeroAcc) {
    int gt = blockIdx.x * blockDim.x + threadIdx.x;
    int node = gt >> 5;
    if (node >= Nn) return;
    int lane = gt & 31;
    float4 v = ((const float4*)g_acc)[node * 32 + lane];
    float s = v.x + v.y + v.z + v.w;
    float q = v.x * v.x + v.y * v.y + v.z * v.z + v.w * v.w;
#pragma unroll
    for (int o = 16; o; o >>= 1) {
        s += __shfl_xor_sync(0xffffffffu, s, o);
        q += __shfl_xor_sync(0xffffffffu, q, o);
    }
    float mean = s * (1.f / 128.f);
    float var  = q * (1.f / 128.f) - mean * mean;
    float rstd = rsqrtf(var + 1e-5f);
    float4 gg = ((const float4*)g)[lane];
    float4 bb = ((const float4*)b)[lane];
    float4 o4;
    o4.x = (v.x - mean) * rstd * gg.x + bb.x;
    o4.y = (v.y - mean) * rstd * gg.y + bb.y;
    o4.z = (v.z - mean) * rstd * gg.z + bb.z;
    o4.w = (v.w - mean) * rstd * gg.w + bb.w;
    if (relu) {
        o4.x = fmaxf(o4.x, 0.f); o4.y = fmaxf(o4.y, 0.f);
        o4.z = fmaxf(o4.z, 0.f); o4.w = fmaxf(o4.w, 0.f);
    }
    __half2 p0 = __halves2half2(__float2half_rn(o4.x), __float2half_rn(o4.y));
    __half2 p1 = __halves2half2(__float2half_rn(o4.z), __float2half_rn(o4.w));
    ((uint2*)g_xh)[node * 32 + lane] = make_uint2(*(unsigned*)&p0, *(unsigned*)&p1);
    if (zeroAcc)
        ((float4*)g_acc)[node * 32 + lane] = make_float4(0.f, 0.f, 0.f, 0.f);
}

__global__ void k_final(const float* __restrict__ W, const float* __restrict__ b,
                        float* __restrict__ out) {
    int gt = blockIdx.x * blockDim.x + threadIdx.x;
    if (gt >= NSEL * NCc) return;
    int i = gt / NCc, c = gt % NCc;
    const float* hr = g_hsel + i * Dd;
    float s = b[c];
#pragma unroll 8
    for (int k = 0; k < Dd; k++) s += hr[k] * W[k * NCc + c];
    out[gt] = s;
}

// ---------------- mega kernel: proj (3 segs) || fallback-copy+acc-zero || edge-count --
__global__ void __launch_bounds__(256)
k_mega(const float* A0, const float* W0, const float* b0, const int* x0, int M0, int K0,
       const float* A1, const float* W1, const float* b1, const int* x1, int M1, int K1,
       const float* A2, const float* W2, const float* b2, const int* x2, int M2, int K2,
       const float* __restrict__ fallback,
       const int* __restrict__ ei, const int* __restrict__ et) {
    int blk = blockIdx.x;
    int tid = threadIdx.x;

    if (blk >= NB_PROJ) {
        if (blk < NB_PROJ + NB_COPY) {
            int i = (blk - NB_PROJ) * 256 + tid;
            if (i < Nn * Dd / 4) {
                if (i >= 45000 * 32) {
                    float4 v = ((const float4*)fallback)[i];
                    __half2 p0 = __halves2half2(__float2half_rn(v.x), __float2half_rn(v.y));
                    __half2 p1 = __halves2half2(__float2half_rn(v.z), __float2half_rn(v.w));
                    ((uint2*)g_xh)[i] = make_uint2(*(unsigned*)&p0, *(unsigned*)&p1);
                }
                ((float4*)g_acc)[i] = make_float4(0.f, 0.f, 0.f, 0.f);
            }
        } else {
            int e = (blk - NB_PROJ - NB_COPY) * 256 + tid;
            if (e < Ee) {
                int r = et[e];
                atomicAdd(&g_icnt[r * Nn + ei[Ee + e]], 1);
                atomicAdd(&g_bcnt[r * NG + (ei[e] >> 6)], 1);
            }
        }
        return;
    }

    // ---- projection GEMM segment ----
    const float *A, *B, *bias;
    const int* rowIdx;
    int M, K, row0;
    if (blk < 157)      { A = A0; B = W0; bias = b0; rowIdx = x0; M = M0; K = K0; row0 = blk * 128; }
    else if (blk < 275) { A = A1; B = W1; bias = b1; rowIdx = x1; M = M1; K = K1; row0 = (blk - 157) * 128; }
    else                { A = A2; B = W2; bias = b2; rowIdx = x2; M = M2; K = K2; row0 = (blk - 275) * 128; }

    __shared__ unsigned As[128][36];
    __shared__ unsigned Bs[32][136];
    float acc[2][8][4];
#pragma unroll
    for (int mt = 0; mt < 2; mt++)
#pragma unroll
        for (int nt = 0; nt < 8; nt++)
#pragma unroll
            for (int q = 0; q < 4; q++) acc[mt][nt][q] = 0.f;

    int lane = tid & 31, wid = tid >> 5;
    int wm = (wid >> 1) * 32;
    int wn = (wid & 1) * 64;

    for (int kb = 0; kb < K; kb += 32) {
#pragma unroll
        for (int it = 0; it < 4; it++) {
            int idx = tid + it * 256;
            int m = idx >> 3;
            int kq = (idx & 7) * 4;
            float4 v = make_float4(0.f, 0.f, 0.f, 0.f);
            int row = row0 + m;
            if (row < M) v = *(const float4*)&A[(size_t)row * K + kb + kq];
            As[m][kq + 0] = f2tf(v.x); As[m][kq + 1] = f2tf(v.y);
            As[m][kq + 2] = f2tf(v.z); As[m][kq + 3] = f2tf(v.w);
        }
#pragma unroll
        for (int it = 0; it < 4; it++) {
            int idx = tid + it * 256;
            int k = idx >> 5;
            int nq = (idx & 31) * 4;
            float4 v = *(const float4*)&B[(size_t)(kb + k) * 128 + nq];
            Bs[k][nq + 0] = f2tf(v.x); Bs[k][nq + 1] = f2tf(v.y);
            Bs[k][nq + 2] = f2tf(v.z); Bs[k][nq + 3] = f2tf(v.w);
        }
        __syncthreads();
#pragma unroll
        for (int ks = 0; ks < 4; ks++) {
            int k0 = ks * 8;
            unsigned af[2][4];
#pragma unroll
            for (int mt = 0; mt < 2; mt++) {
                int r = wm + mt * 16 + (lane >> 2);
                int c = k0 + (lane & 3);
                af[mt][0] = As[r][c];     af[mt][1] = As[r + 8][c];
                af[mt][2] = As[r][c + 4]; af[mt][3] = As[r + 8][c + 4];
            }
#pragma unroll
            for (int nt = 0; nt < 8; nt++) {
                unsigned bf[2];
                int br = k0 + (lane & 3);
                int bc = wn + nt * 8 + (lane >> 2);
                bf[0] = Bs[br][bc];
                bf[1] = Bs[br + 4][bc];
                mma_tf32(acc[0][nt], af[0], bf);
                mma_tf32(acc[1][nt], af[1], bf);
            }
        }
        __syncthreads();
    }

#pragma unroll
    for (int mt = 0; mt < 2; mt++) {
#pragma unroll
        for (int h = 0; h < 2; h++) {
            int row = row0 + wm + mt * 16 + (lane >> 2) + h * 8;
            if (row >= M) continue;
            int cr = rowIdx[row];
#pragma unroll
            for (int nt = 0; nt < 8; nt++) {
                int col = wn + nt * 8 + 2 * (lane & 3);
                float v0 = acc[mt][nt][h * 2 + 0] + bias[col];
                float v1 = acc[mt][nt][h * 2 + 1] + bias[col + 1];
                __half2 p = __halves2half2(__float2half_rn(v0), __float2half_rn(v1));
                *(unsigned*)&g_xh[(size_t)cr * 128 + col] = *(unsigned*)&p;
            }
        }
    }
}

// ---------------- classifier GEMM: half input (exact cvt), tf32 math, f32 out ----
__global__ void __launch_bounds__(256)
cgemm(const int* __restrict__ aIdx, const float* __restrict__ B,
      const float* __restrict__ bias) {
    int row0 = blockIdx.x * 128;
    __shared__ unsigned As[128][36];
    __shared__ unsigned Bs[32][136];
    float acc[2][8][4];
#pragma unroll
    for (int mt = 0; mt < 2; mt++)
#pragma unroll
        for (int nt = 0; nt < 8; nt++)
#pragma unroll
            for (int q = 0; q < 4; q++) acc[mt][nt][q] = 0.f;

    int tid = threadIdx.x;
    int lane = tid & 31, wid = tid >> 5;
    int wm = (wid >> 1) * 32;
    int wn = (wid & 1) * 64;

    for (int kb = 0; kb < 128; kb += 32) {
#pragma unroll
        for (int it = 0; it < 4; it++) {
            int idx = tid + it * 256;
            int m = idx >> 3;
            int kq = (idx & 7) * 4;
            int row = row0 + m;
            int ar = aIdx[row];
            const __half* src = &g_xh[(size_t)ar * 128 + kb + kq];
            As[m][kq + 0] = f2tf(__half2float(src[0]));
            As[m][kq + 1] = f2tf(__half2float(src[1]));
            As[m][kq + 2] = f2tf(__half2float(src[2]));
            As[m][kq + 3] = f2tf(__half2float(src[3]));
        }
#pragma unroll
        for (int it = 0; it < 4; it++) {
            int idx = tid + it * 256;
            int k = idx >> 5;
            int nq = (idx & 31) * 4;
            float4 v = *(const float4*)&B[(size_t)(kb + k) * 128 + nq];
            Bs[k][nq + 0] = f2tf(v.x); Bs[k][nq + 1] = f2tf(v.y);
            Bs[k][nq + 2] = f2tf(v.z); Bs[k][nq + 3] = f2tf(v.w);
        }
        __syncthreads();
#pragma unroll
        for (int ks = 0; ks < 4; ks++) {
            int k0 = ks * 8;
            unsigned af[2][4];
#pragma unroll
            for (int mt = 0; mt < 2; mt++) {
                int r = wm + mt * 16 + (lane >> 2);
                int c = k0 + (lane & 3);
                af[mt][0] = As[r][c];     af[mt][1] = As[r + 8][c];
                af[mt][2] = As[r][c + 4]; af[mt][3] = As[r + 8][c + 4];
            }
#pragma unroll
            for (int nt = 0; nt < 8; nt++) {
                unsigned bf[2];
                int br = k0 + (lane & 3);
                int bc = wn + nt * 8 + (lane >> 2);
                bf[0] = Bs[br][bc];
                bf[1] = Bs[br + 4][bc];
                mma_tf32(acc[0][nt], af[0], bf);
                mma_tf32(acc[1][nt], af[1], bf);
            }
        }
        __syncthreads();
    }

#pragma unroll
    for (int mt = 0; mt < 2; mt++) {
#pragma unroll
        for (int h = 0; h < 2; h++) {
            int row = row0 + wm + mt * 16 + (lane >> 2) + h * 8;
#pragma unroll
            for (int nt = 0; nt < 8; nt++) {
                int col = wn + nt * 8 + 2 * (lane & 3);
                float v0 = fmaxf(acc[mt][nt][h * 2 + 0] + bias[col], 0.f);
                float v1 = fmaxf(acc[mt][nt][h * 2 + 1] + bias[col + 1], 0.f);
                *(float2*)&g_hsel[(size_t)row * 128 + col] = make_float2(v0, v1);
            }
        }
    }
}

// ---------------- fp16 fused dense GEMM + edge scatter (single-phase epilogue) ------
// grid = (NTILE, SLOTS) — 4301 independent blocks: cross-block MMA/scatter overlap.
__global__ void __launch_bounds__(256, 2)
ftg_h(const float* __restrict__ bias, int layer) {
    extern __shared__ __align__(16) char dsm[];
    __half (*As)[136] = (__half(*)[136])dsm;
    __half (*Bs)[136] = (__half(*)[136])(dsm + SMH_A_BYTES);
    float  (*Ch)[CH_STRIDE] = (float(*)[CH_STRIDE])dsm;   // overlays A+B after MMA

    int tile = blockIdx.x;
    int r    = blockIdx.y;
    int row0 = tile * 128;
    bool isRoot = (r == Rr);

    int bkt0 = 0;
    if (!isRoot) {
        bkt0 = r * NG + tile * 2;
        if (g_boff[bkt0] == g_boff[bkt0 + 2]) return;
    }

    int tid = threadIdx.x;
    int lane = tid & 31, wid = tid >> 5;
    int wm = (wid >> 1) * 32;
    int wn = (wid & 1) * 64;

    const __half* Wz = g_Wh + (size_t)(layer * SLOTS + r) * (Dd * Dd);

#pragma unroll
    for (int it = 0; it < 8; it++) {
        int idx = tid + it * 256;
        int m = idx >> 4, c8 = (idx & 15) * 8;
        int gr = row0 + m;
        cp16(&As[m][c8], &g_xh[(size_t)gr * 128 + c8], gr < Nn ? 16 : 0);
    }
#pragma unroll
    for (int it = 0; it < 8; it++) {
        int idx = tid + it * 256;
        int n = idx >> 4, c8 = (idx & 15) * 8;
        cp16(&Bs[n][c8], &Wz[(size_t)n * 128 + c8], 16);
    }
    asm volatile("cp.async.commit_group;");

    float acc[2][8][4];
#pragma unroll
    for (int mt = 0; mt < 2; mt++)
#pragma unroll
        for (int nt = 0; nt < 8; nt++)
#pragma unroll
            for (int q = 0; q < 4; q++) acc[mt][nt][q] = 0.f;

    // ldmatrix base addresses
    int l7 = lane & 7, lm = (lane >> 3) & 1, lh = lane >> 4;
    uint32_t aAddr[2], bAddr[4];
#pragma unroll
    for (int mt = 0; mt < 2; mt++)
        aAddr[mt] = sma(&As[wm + mt * 16 + lm * 8 + l7][lh * 8]);
#pragma unroll
    for (int p = 0; p < 4; p++)
        bAddr[p] = sma(&Bs[wn + (2 * p + lh) * 8 + l7][lm * 8]);

    asm volatile("cp.async.wait_group 0;" ::: "memory");
    __syncthreads();

#pragma unroll
    for (int ks = 0; ks < 8; ks++) {
        uint32_t off = ks * 32;
        unsigned a0[4], a1[4];
        ldsm4(a0[0], a0[1], a0[2], a0[3], aAddr[0] + off);
        ldsm4(a1[0], a1[1], a1[2], a1[3], aAddr[1] + off);
#pragma unroll
        for (int p = 0; p < 4; p++) {
            unsigned b0, b1, b2, b3;
            ldsm4(b0, b1, b2, b3, bAddr[p] + off);
            mma_f16(acc[0][2 * p + 0], a0[0], a0[1], a0[2], a0[3], b0, b1);
            mma_f16(acc[0][2 * p + 1], a0[0], a0[1], a0[2], a0[3], b2, b3);
            mma_f16(acc[1][2 * p + 0], a1[0], a1[1], a1[2], a1[3], b0, b1);
            mma_f16(acc[1][2 * p + 1], a1[0], a1[1], a1[2], a1[3], b2, b3);
        }
    }

    if (isRoot) {
#pragma unroll
        for (int mt = 0; mt < 2; mt++)
#pragma unroll
            for (int h = 0; h < 2; h++) {
                int row = row0 + wm + mt * 16 + (lane >> 2) + h * 8;
                if (row >= Nn) continue;
                float* outr = g_acc + (size_t)row * 128;
#pragma unroll
                for (int nt = 0; nt < 8; nt++) {
                    int col = wn + nt * 8 + 2 * (lane & 3);
                    float v0 = acc[mt][nt][h * 2 + 0] + bias[col];
                    float v1 = acc[mt][nt][h * 2 + 1] + bias[col + 1];
                    asm volatile("red.global.add.v2.f32 [%0], {%1,%2};"
                                 :: "l"(outr + col), "f"(v0), "f"(v1) : "memory");
                }
            }
        return;
    }

    __syncthreads();   // all warps done with A/B smem (ldmatrix) before Ch overlay

    // stage full 128-row tile into Ch (all 8 warps write their own acc rows)
#pragma unroll
    for (int mt = 0; mt < 2; mt++)
#pragma unroll
        for (int h = 0; h < 2; h++) {
            int rl = wm + mt * 16 + h * 8 + (lane >> 2);
#pragma unroll
            for (int nt = 0; nt < 8; nt++) {
                int col = wn + nt * 8 + 2 * (lane & 3);
                *(float2*)&Ch[rl][col] =
                    make_float2(acc[mt][nt][h * 2 + 0], acc[mt][nt][h * 2 + 1]);
            }
        }
    __syncthreads();

    // single scatter loop over the contiguous bucket pair (pipelined, packed metadata)
    int lo = g_boff[bkt0], hi = g_boff[bkt0 + 2];
    int i = lo + wid;
    int2 nm = make_int2(0, 0);
    if (i < hi) nm = g_bmeta[i];
    while (i < hi) {
        int meta = nm.x;
        float w  = __int_as_float(nm.y);
        int inext = i + 8;
        if (inext < hi) nm = g_bmeta[inext];
        int sloc = (meta >> 17) & 127;
        int dst  = meta & 0x1FFFF;
        float4 v = *(const float4*)&Ch[sloc][lane * 4];
        v.x *= w; v.y *= w; v.z *= w; v.w *= w;
        float* p = g_acc + (size_t)dst * 128 + lane * 4;
        asm volatile("red.global.add.v4.f32 [%0], {%1,%2,%3,%4};"
                     :: "l"(p), "f"(v.x), "f"(v.y), "f"(v.z), "f"(v.w) : "memory");
        i = inext;
    }
}

// ---------------- launch ----------------
extern "C" void kernel_launch(void* const* d_in, const int* in_sizes, int n_in,
                              void* d_out, int out_size) {
    const int*   edge_index   = (const int*)d_in[0];
    const int*   edge_type    = (const int*)d_in[1];
    const int*   node_indices = (const int*)d_in[2];
    const float* file_feats   = (const float*)d_in[3];
    const int*   file_idx     = (const int*)d_in[4];
    const float* domain_feats = (const float*)d_in[5];
    const int*   domain_idx   = (const int*)d_in[6];
    const float* ip_feats     = (const float*)d_in[7];
    const int*   ip_idx       = (const int*)d_in[8];
    const float* fallback     = (const float*)d_in[9];
    const float* Wf  = (const float*)d_in[10];
    const float* bf  = (const float*)d_in[11];
    const float* Wd  = (const float*)d_in[12];
    const float* bd  = (const float*)d_in[13];
    const float* Wi  = (const float*)d_in[14];
    const float* bi  = (const float*)d_in[15];
    const float* comp1  = (const float*)d_in[16];
    const float* bases1 = (const float*)d_in[17];
    const float* root1  = (const float*)d_in[18];
    const float* bias1  = (const float*)d_in[19];
    const float* comp2  = (const float*)d_in[20];
    const float* bases2 = (const float*)d_in[21];
    const float* root2  = (const float*)d_in[22];
    const float* bias2  = (const float*)d_in[23];
    const float* ln1_g  = (const float*)d_in[24];
    const float* ln1_b  = (const float*)d_in[25];
    const float* ln2_g  = (const float*)d_in[26];
    const float* ln2_b  = (const float*)d_in[27];
    const float* Wc1 = (const float*)d_in[28];
    const float* bc1 = (const float*)d_in[29];
    const float* Wc2 = (const float*)d_in[30];
    const float* bc2 = (const float*)d_in[31];
    float* out = (float*)d_out;

    static int smem_set = 0;
    if (!smem_set) {
        cudaFuncSetAttribute(ftg_h, cudaFuncAttributeMaxDynamicSharedMemorySize, SMH_TOTAL);
        smem_set = 1;
    }

    // ---- zero counters, then fused proj || copy/acc-zero || count ----
    k_zero<<<(Rr * Nn + 255) / 256, 256>>>();
    k_mega<<<NB_PROJ + NB_COPY + NB_CNT, 256>>>(
        file_feats,   Wf, bf, file_idx,   20000, 256,
        domain_feats, Wd, bd, domain_idx, 15000, 128,
        ip_feats,     Wi, bi, ip_idx,     10000, 64,
        fallback, edge_index, edge_type);

    // ---- both layers' W + bucket scan (fused) ----
    k_setup<<<dim3(NB_BW + 1, 2), 1024>>>(comp1, bases1, root1, comp2, bases2, root2);

    // ---- place edges (packed metadata) ----
    k_place<<<(Ee + 255) / 256, 256>>>(edge_index, edge_type);

    dim3 fgrid(NTILE, SLOTS);

    // ---- layer 1 ----
    ftg_h<<<fgrid, 256, SMH_TOTAL>>>(bias1, 0);
    k_ln<<<(Nn * 32 + 255) / 256, 256>>>(ln1_g, ln1_b, 1, 1);

    // ---- layer 2 ----
    ftg_h<<<fgrid, 256, SMH_TOTAL>>>(bias2, 1);
    k_ln<<<(Nn * 32 + 255) / 256, 256>>>(ln2_g, ln2_b, 0, 0);

    // ---- classifier ----
    cgemm<<<NSEL / 128, 256>>>(node_indices, Wc1, bc1);
    k_final<<<(NSEL * NCc + 255) / 256, 256>>>(Wc2, bc2, out);
}

// round 16
// speedup vs baseline: 1.4434x; 1.0703x over previous
#include <cuda_runtime.h>
#include <cuda_fp16.h>
#include <cstdint>

// Problem constants
#define Nn    50000
#define Dd    128
#define Rr    10
#define Ee    800000
#define NSEL  8192
#define NCc   12
#define NTILE 391                 // ceil(Nn/128)
#define NG    782                 // ceil(Nn/64) src groups
#define NBKT  (Rr * NG)
#define SLOTS (Rr + 1)            // 10 relations + root

// ftg_h smem: A half[128][136] + B half[128][136]; Ch f32[128][132] overlays A+B
#define SMH_A_BYTES (128 * 136 * 2)     // 34816
#define SMH_TOTAL   (2 * SMH_A_BYTES)   // 69632  (Ch needs 67584 <= this)
#define CH_STRIDE   132

// mega-kernel block ranges
#define NB_PROJ  354      // 157 + 118 + 79
#define NB_COPY  6250     // Nn*Dd/4 / 256
#define NB_CNT   3125     // Ee / 256

// k_setup: build-W blocks (1024 thr) + 1 scan block
#define NB_BW    176      // SLOTS*Dd*Dd / 1024

// ---------------- device scratch ----------------
__device__ __half g_xh[Nn * Dd];              // node features, fp16
__device__ float  g_acc[Nn * Dd];             // conv accumulator (fp32)
__device__ __half g_Wh[2 * SLOTS * Dd * Dd];  // both layers' W^T [layer][slot][n][k]
__device__ int    g_icnt[Rr * Nn];
__device__ float  g_hsel[NSEL * Dd];
__device__ int    g_bcnt[NBKT];
__device__ int    g_bcur[NBKT];
__device__ int    g_boff[NBKT + 1];
__device__ int2   g_bmeta[Ee];                // {sloc<<17|dst, f32bits(w)}

// ---------------- helpers ----------------
__device__ __forceinline__ unsigned f2tf(float f) {
    unsigned u;
    asm("cvt.rna.tf32.f32 %0, %1;" : "=r"(u) : "f"(f));
    return u;
}

__device__ __forceinline__ void mma_tf32(float c[4], const unsigned a[4], const unsigned b[2]) {
    asm volatile("mma.sync.aligned.m16n8k8.row.col.f32.tf32.tf32.f32 "
                 "{%0,%1,%2,%3}, {%4,%5,%6,%7}, {%8,%9}, {%0,%1,%2,%3};"
                 : "+f"(c[0]), "+f"(c[1]), "+f"(c[2]), "+f"(c[3])
                 : "r"(a[0]), "r"(a[1]), "r"(a[2]), "r"(a[3]), "r"(b[0]), "r"(b[1]));
}

__device__ __forceinline__ void mma_f16(float c[4], unsigned a0, unsigned a1,
                                        unsigned a2, unsigned a3,
                                        unsigned b0, unsigned b1) {
    asm volatile("mma.sync.aligned.m16n8k16.row.col.f32.f16.f16.f32 "
                 "{%0,%1,%2,%3}, {%4,%5,%6,%7}, {%8,%9}, {%0,%1,%2,%3};"
                 : "+f"(c[0]), "+f"(c[1]), "+f"(c[2]), "+f"(c[3])
                 : "r"(a0), "r"(a1), "r"(a2), "r"(a3), "r"(b0), "r"(b1));
}

__device__ __forceinline__ void cp16(void* smem, const void* g, int srcsize) {
    unsigned a = (unsigned)__cvta_generic_to_shared(smem);
    asm volatile("cp.async.ca.shared.global [%0], [%1], 16, %2;"
                 :: "r"(a), "l"(g), "r"(srcsize));
}

__device__ __forceinline__ void ldsm4(unsigned& r0, unsigned& r1, unsigned& r2, unsigned& r3,
                                      uint32_t addr) {
    asm volatile("ldmatrix.sync.aligned.m8n8.x4.shared.b16 {%0,%1,%2,%3}, [%4];"
                 : "=r"(r0), "=r"(r1), "=r"(r2), "=r"(r3) : "r"(addr));
}

__device__ __forceinline__ uint32_t sma(const void* p) {
    return (uint32_t)__cvta_generic_to_shared(p);
}

// ---------------- small kernels ----------------
__global__ void k_zero() {
    int i = blockIdx.x * blockDim.x + threadIdx.x;
    if (i < Rr * Nn) g_icnt[i] = 0;
    if (i < NBKT) { g_bcnt[i] = 0; g_bcur[i] = 0; }
}

// fused: builds both layers' W^T (fp16) AND runs the bucket scan in the last block.
__global__ void k_setup(const float* __restrict__ comp1, const float* __restrict__ bases1,
                        const float* __restrict__ root1,
                        const float* __restrict__ comp2, const float* __restrict__ bases2,
                        const float* __restrict__ root2) {
    int t = threadIdx.x;
    if (blockIdx.x == NB_BW) {
        if (blockIdx.y != 0) return;
        __shared__ int wsum[32];
        int lane = t & 31, wid = t >> 5;
        int cnt[8];
        int s = 0;
#pragma unroll
        for (int j = 0; j < 8; j++) {
            int b = t * 8 + j;
            cnt[j] = (b < NBKT) ? g_bcnt[b] : 0;
            s += cnt[j];
        }
        int incl = s;
#pragma unroll
        for (int o = 1; o < 32; o <<= 1) {
            int v = __shfl_up_sync(0xffffffffu, incl, o);
            if (lane >= o) incl += v;
        }
        if (lane == 31) wsum[wid] = incl;
        __syncthreads();
        if (wid == 0) {
            int v = wsum[lane];
            int iv = v;
#pragma unroll
            for (int o = 1; o < 32; o <<= 1) {
                int u = __shfl_up_sync(0xffffffffu, iv, o);
                if (lane >= o) iv += u;
            }
            wsum[lane] = iv - v;
            if (lane == 31) g_boff[NBKT] = iv;
        }
        __syncthreads();
        int run = wsum[wid] + (incl - s);
#pragma unroll
        for (int j = 0; j < 8; j++) {
            int b = t * 8 + j;
            if (b < NBKT) { g_boff[b] = run; run += cnt[j]; }
        }
        return;
    }
    int i = blockIdx.x * 1024 + t;
    int layer = blockIdx.y;
    const float* comp  = layer ? comp2  : comp1;
    const float* bases = layer ? bases2 : bases1;
    const float* root  = layer ? root2  : root1;
    int slot = i >> 14;
    int idx  = i & 16383;          // n*128 + k
    int n = idx >> 7, k = idx & 127;
    int src = k * 128 + n;
    float v;
    if (slot < Rr) {
        v = 0.f;
#pragma unroll
        for (int b = 0; b < 4; b++)
            v += comp[slot * 4 + b] * bases[b * Dd * Dd + src];
    } else {
        v = root[src];
    }
    g_Wh[layer * SLOTS * Dd * Dd + i] = __float2half_rn(v);
}

// places edges (2 per thread, both random loads issued before atomics)
__global__ void k_place(const int* __restrict__ ei, const int* __restrict__ et) {
    int e0 = (blockIdx.x * blockDim.x + threadIdx.x) * 2;
    if (e0 >= Ee) return;
    int e1 = e0 + 1;
    bool has1 = (e1 < Ee);

    int r0 = et[e0], s0 = ei[e0], t0 = ei[Ee + e0];
    int r1 = 0, s1 = 0, t1 = 0;
    if (has1) { r1 = et[e1]; s1 = ei[e1]; t1 = ei[Ee + e1]; }

    int c0 = g_icnt[r0 * Nn + t0];
    int c1 = has1 ? g_icnt[r1 * Nn + t1] : 1;

    int key0 = r0 * NG + (s0 >> 6);
    int pos0 = g_boff[key0] + atomicAdd(&g_bcur[key0], 1);
    float w0 = 1.0f / fmaxf((float)c0, 1.0f);
    g_bmeta[pos0] = make_int2(((s0 & 127) << 17) | t0, __float_as_int(w0));

    if (has1) {
        int key1 = r1 * NG + (s1 >> 6);
        int pos1 = g_boff[key1] + atomicAdd(&g_bcur[key1], 1);
        float w1 = 1.0f / fmaxf((float)c1, 1.0f);
        g_bmeta[pos1] = make_int2(((s1 & 127) << 17) | t1, __float_as_int(w1));
    }
}

// one warp per node: LayerNorm (+optional ReLU) -> g_xh (fp16); optionally zeroes acc
__global__ void k_ln(const float* __restrict__ g, const float* __restrict__ b,
                     int relu, int zeroAcc) {
    int gt = blockIdx.x * blockDim.x + threadIdx.x;
    int node = gt >> 5;
    if (node >= Nn) return;
    int lane = gt & 31;
    float4 v = ((const float4*)g_acc)[node * 32 + lane];
    float s = v.x + v.y + v.z + v.w;
    float q = v.x * v.x + v.y * v.y + v.z * v.z + v.w * v.w;
#pragma unroll
    for (int o = 16; o; o >>= 1) {
        s += __shfl_xor_sync(0xffffffffu, s, o);
        q += __shfl_xor_sync(0xffffffffu, q, o);
    }
    float mean = s * (1.f / 128.f);
    float var  = q * (1.f / 128.f) - mean * mean;
    float rstd = rsqrtf(var + 1e-5f);
    float4 gg = ((const float4*)g)[lane];
    float4 bb = ((const float4*)b)[lane];
    float4 o4;
    o4.x = (v.x - mean) * rstd * gg.x + bb.x;
    o4.y = (v.y - mean) * rstd * gg.y + bb.y;
    o4.z = (v.z - mean) * rstd * gg.z + bb.z;
    o4.w = (v.w - mean) * rstd * gg.w + bb.w;
    if (relu) {
        o4.x = fmaxf(o4.x, 0.f); o4.y = fmaxf(o4.y, 0.f);
        o4.z = fmaxf(o4.z, 0.f); o4.w = fmaxf(o4.w, 0.f);
    }
    __half2 p0 = __halves2half2(__float2half_rn(o4.x), __float2half_rn(o4.y));
    __half2 p1 = __halves2half2(__float2half_rn(o4.z), __float2half_rn(o4.w));
    ((uint2*)g_xh)[node * 32 + lane] = make_uint2(*(unsigned*)&p0, *(unsigned*)&p1);
    if (zeroAcc)
        ((float4*)g_acc)[node * 32 + lane] = make_float4(0.f, 0.f, 0.f, 0.f);
}

__global__ void k_final(const float* __restrict__ W, const float* __restrict__ b,
                        float* __restrict__ out) {
    int gt = blockIdx.x * blockDim.x + threadIdx.x;
    if (gt >= NSEL * NCc) return;
    int i = gt / NCc, c = gt % NCc;
    const float* hr = g_hsel + i * Dd;
    float s = b[c];
#pragma unroll 8
    for (int k = 0; k < Dd; k++) s += hr[k] * W[k * NCc + c];
    out[gt] = s;
}

// ---------------- mega kernel: proj (3 segs) || fallback-copy+acc-zero || edge-count --
__global__ void __launch_bounds__(256)
k_mega(const float* A0, const float* W0, const float* b0, const int* x0, int M0, int K0,
       const float* A1, const float* W1, const float* b1, const int* x1, int M1, int K1,
       const float* A2, const float* W2, const float* b2, const int* x2, int M2, int K2,
       const float* __restrict__ fallback,
       const int* __restrict__ ei, const int* __restrict__ et) {
    int blk = blockIdx.x;
    int tid = threadIdx.x;

    if (blk >= NB_PROJ) {
        if (blk < NB_PROJ + NB_COPY) {
            int i = (blk - NB_PROJ) * 256 + tid;
            if (i < Nn * Dd / 4) {
                if (i >= 45000 * 32) {
                    float4 v = ((const float4*)fallback)[i];
                    __half2 p0 = __halves2half2(__float2half_rn(v.x), __float2half_rn(v.y));
                    __half2 p1 = __halves2half2(__float2half_rn(v.z), __float2half_rn(v.w));
                    ((uint2*)g_xh)[i] = make_uint2(*(unsigned*)&p0, *(unsigned*)&p1);
                }
                ((float4*)g_acc)[i] = make_float4(0.f, 0.f, 0.f, 0.f);
            }
        } else {
            int e = (blk - NB_PROJ - NB_COPY) * 256 + tid;
            if (e < Ee) {
                int r = et[e];
                atomicAdd(&g_icnt[r * Nn + ei[Ee + e]], 1);
                atomicAdd(&g_bcnt[r * NG + (ei[e] >> 6)], 1);
            }
        }
        return;
    }

    // ---- projection GEMM segment ----
    const float *A, *B, *bias;
    const int* rowIdx;
    int M, K, row0;
    if (blk < 157)      { A = A0; B = W0; bias = b0; rowIdx = x0; M = M0; K = K0; row0 = blk * 128; }
    else if (blk < 275) { A = A1; B = W1; bias = b1; rowIdx = x1; M = M1; K = K1; row0 = (blk - 157) * 128; }
    else                { A = A2; B = W2; bias = b2; rowIdx = x2; M = M2; K = K2; row0 = (blk - 275) * 128; }

    __shared__ unsigned As[128][36];
    __shared__ unsigned Bs[32][136];
    float acc[2][8][4];
#pragma unroll
    for (int mt = 0; mt < 2; mt++)
#pragma unroll
        for (int nt = 0; nt < 8; nt++)
#pragma unroll
            for (int q = 0; q < 4; q++) acc[mt][nt][q] = 0.f;

    int lane = tid & 31, wid = tid >> 5;
    int wm = (wid >> 1) * 32;
    int wn = (wid & 1) * 64;

    for (int kb = 0; kb < K; kb += 32) {
#pragma unroll
        for (int it = 0; it < 4; it++) {
            int idx = tid + it * 256;
            int m = idx >> 3;
            int kq = (idx & 7) * 4;
            float4 v = make_float4(0.f, 0.f, 0.f, 0.f);
            int row = row0 + m;
            if (row < M) v = *(const float4*)&A[(size_t)row * K + kb + kq];
            As[m][kq + 0] = f2tf(v.x); As[m][kq + 1] = f2tf(v.y);
            As[m][kq + 2] = f2tf(v.z); As[m][kq + 3] = f2tf(v.w);
        }
#pragma unroll
        for (int it = 0; it < 4; it++) {
            int idx = tid + it * 256;
            int k = idx >> 5;
            int nq = (idx & 31) * 4;
            float4 v = *(const float4*)&B[(size_t)(kb + k) * 128 + nq];
            Bs[k][nq + 0] = f2tf(v.x); Bs[k][nq + 1] = f2tf(v.y);
            Bs[k][nq + 2] = f2tf(v.z); Bs[k][nq + 3] = f2tf(v.w);
        }
        __syncthreads();
#pragma unroll
        for (int ks = 0; ks < 4; ks++) {
            int k0 = ks * 8;
            unsigned af[2][4];
#pragma unroll
            for (int mt = 0; mt < 2; mt++) {
                int r = wm + mt * 16 + (lane >> 2);
                int c = k0 + (lane & 3);
                af[mt][0] = As[r][c];     af[mt][1] = As[r + 8][c];
                af[mt][2] = As[r][c + 4]; af[mt][3] = As[r + 8][c + 4];
            }
#pragma unroll
            for (int nt = 0; nt < 8; nt++) {
                unsigned bf[2];
                int br = k0 + (lane & 3);
                int bc = wn + nt * 8 + (lane >> 2);
                bf[0] = Bs[br][bc];
                bf[1] = Bs[br + 4][bc];
                mma_tf32(acc[0][nt], af[0], bf);
                mma_tf32(acc[1][nt], af[1], bf);
            }
        }
        __syncthreads();
    }

#pragma unroll
    for (int mt = 0; mt < 2; mt++) {
#pragma unroll
        for (int h = 0; h < 2; h++) {
            int row = row0 + wm + mt * 16 + (lane >> 2) + h * 8;
            if (row >= M) continue;
            int cr = rowIdx[row];
#pragma unroll
            for (int nt = 0; nt < 8; nt++) {
                int col = wn + nt * 8 + 2 * (lane & 3);
                float v0 = acc[mt][nt][h * 2 + 0] + bias[col];
                float v1 = acc[mt][nt][h * 2 + 1] + bias[col + 1];
                __half2 p = __halves2half2(__float2half_rn(v0), __float2half_rn(v1));
                *(unsigned*)&g_xh[(size_t)cr * 128 + col] = *(unsigned*)&p;
            }
        }
    }
}

// ---------------- classifier GEMM: half input (exact cvt), tf32 math, f32 out ----
__global__ void __launch_bounds__(256)
cgemm(const int* __restrict__ aIdx, const float* __restrict__ B,
      const float* __restrict__ bias) {
    int row0 = blockIdx.x * 128;
    __shared__ unsigned As[128][36];
    __shared__ unsigned Bs[32][136];
    float acc[2][8][4];
#pragma unroll
    for (int mt = 0; mt < 2; mt++)
#pragma unroll
        for (int nt = 0; nt < 8; nt++)
#pragma unroll
            for (int q = 0; q < 4; q++) acc[mt][nt][q] = 0.f;

    int tid = threadIdx.x;
    int lane = tid & 31, wid = tid >> 5;
    int wm = (wid >> 1) * 32;
    int wn = (wid & 1) * 64;

    for (int kb = 0; kb < 128; kb += 32) {
#pragma unroll
        for (int it = 0; it < 4; it++) {
            int idx = tid + it * 256;
            int m = idx >> 3;
            int kq = (idx & 7) * 4;
            int row = row0 + m;
            int ar = aIdx[row];
            const __half* src = &g_xh[(size_t)ar * 128 + kb + kq];
            As[m][kq + 0] = f2tf(__half2float(src[0]));
            As[m][kq + 1] = f2tf(__half2float(src[1]));
            As[m][kq + 2] = f2tf(__half2float(src[2]));
            As[m][kq + 3] = f2tf(__half2float(src[3]));
        }
#pragma unroll
        for (int it = 0; it < 4; it++) {
            int idx = tid + it * 256;
            int k = idx >> 5;
            int nq = (idx & 31) * 4;
            float4 v = *(const float4*)&B[(size_t)(kb + k) * 128 + nq];
            Bs[k][nq + 0] = f2tf(v.x); Bs[k][nq + 1] = f2tf(v.y);
            Bs[k][nq + 2] = f2tf(v.z); Bs[k][nq + 3] = f2tf(v.w);
        }
        __syncthreads();
#pragma unroll
        for (int ks = 0; ks < 4; ks++) {
            int k0 = ks * 8;
            unsigned af[2][4];
#pragma unroll
            for (int mt = 0; mt < 2; mt++) {
                int r = wm + mt * 16 + (lane >> 2);
                int c = k0 + (lane & 3);
                af[mt][0] = As[r][c];     af[mt][1] = As[r + 8][c];
                af[mt][2] = As[r][c + 4]; af[mt][3] = As[r + 8][c + 4];
            }
#pragma unroll
            for (int nt = 0; nt < 8; nt++) {
                unsigned bf[2];
                int br = k0 + (lane & 3);
                int bc = wn + nt * 8 + (lane >> 2);
                bf[0] = Bs[br][bc];
                bf[1] = Bs[br + 4][bc];
                mma_tf32(acc[0][nt], af[0], bf);
                mma_tf32(acc[1][nt], af[1], bf);
            }
        }
        __syncthreads();
    }

#pragma unroll
    for (int mt = 0; mt < 2; mt++) {
#pragma unroll
        for (int h = 0; h < 2; h++) {
            int row = row0 + wm + mt * 16 + (lane >> 2) + h * 8;
#pragma unroll
            for (int nt = 0; nt < 8; nt++) {
                int col = wn + nt * 8 + 2 * (lane & 3);
                float v0 = fmaxf(acc[mt][nt][h * 2 + 0] + bias[col], 0.f);
                float v1 = fmaxf(acc[mt][nt][h * 2 + 1] + bias[col + 1], 0.f);
                *(float2*)&g_hsel[(size_t)row * 128 + col] = make_float2(v0, v1);
            }
        }
    }
}

// ---------------- fp16 fused dense GEMM + edge scatter (single-phase epilogue) ------
// grid = (NTILE, SLOTS) — 4301 independent blocks: cross-block MMA/scatter overlap.
__global__ void __launch_bounds__(256, 2)
ftg_h(const float* __restrict__ bias, int layer) {
    extern __shared__ __align__(16) char dsm[];
    __half (*As)[136] = (__half(*)[136])dsm;
    __half (*Bs)[136] = (__half(*)[136])(dsm + SMH_A_BYTES);
    float  (*Ch)[CH_STRIDE] = (float(*)[CH_STRIDE])dsm;   // overlays A+B after MMA

    int tile = blockIdx.x;
    int r    = blockIdx.y;
    int row0 = tile * 128;
    bool isRoot = (r == Rr);

    int bkt0 = 0;
    if (!isRoot) {
        bkt0 = r * NG + tile * 2;
        if (g_boff[bkt0] == g_boff[bkt0 + 2]) return;
    }

    int tid = threadIdx.x;
    int lane = tid & 31, wid = tid >> 5;
    int wm = (wid >> 1) * 32;
    int wn = (wid & 1) * 64;

    const __half* Wz = g_Wh + (size_t)(layer * SLOTS + r) * (Dd * Dd);

#pragma unroll
    for (int it = 0; it < 8; it++) {
        int idx = tid + it * 256;
        int m = idx >> 4, c8 = (idx & 15) * 8;
        int gr = row0 + m;
        cp16(&As[m][c8], &g_xh[(size_t)gr * 128 + c8], gr < Nn ? 16 : 0);
    }
#pragma unroll
    for (int it = 0; it < 8; it++) {
        int idx = tid + it * 256;
        int n = idx >> 4, c8 = (idx & 15) * 8;
        cp16(&Bs[n][c8], &Wz[(size_t)n * 128 + c8], 16);
    }
    asm volatile("cp.async.commit_group;");

    float acc[2][8][4];
#pragma unroll
    for (int mt = 0; mt < 2; mt++)
#pragma unroll
        for (int nt = 0; nt < 8; nt++)
#pragma unroll
            for (int q = 0; q < 4; q++) acc[mt][nt][q] = 0.f;

    // ldmatrix base addresses
    int l7 = lane & 7, lm = (lane >> 3) & 1, lh = lane >> 4;
    uint32_t aAddr[2], bAddr[4];
#pragma unroll
    for (int mt = 0; mt < 2; mt++)
        aAddr[mt] = sma(&As[wm + mt * 16 + lm * 8 + l7][lh * 8]);
#pragma unroll
    for (int p = 0; p < 4; p++)
        bAddr[p] = sma(&Bs[wn + (2 * p + lh) * 8 + l7][lm * 8]);

    asm volatile("cp.async.wait_group 0;" ::: "memory");
    __syncthreads();

#pragma unroll
    for (int ks = 0; ks < 8; ks++) {
        uint32_t off = ks * 32;
        unsigned a0[4], a1[4];
        ldsm4(a0[0], a0[1], a0[2], a0[3], aAddr[0] + off);
        ldsm4(a1[0], a1[1], a1[2], a1[3], aAddr[1] + off);
#pragma unroll
        for (int p = 0; p < 4; p++) {
            unsigned b0, b1, b2, b3;
            ldsm4(b0, b1, b2, b3, bAddr[p] + off);
            mma_f16(acc[0][2 * p + 0], a0[0], a0[1], a0[2], a0[3], b0, b1);
            mma_f16(acc[0][2 * p + 1], a0[0], a0[1], a0[2], a0[3], b2, b3);
            mma_f16(acc[1][2 * p + 0], a1[0], a1[1], a1[2], a1[3], b0, b1);
            mma_f16(acc[1][2 * p + 1], a1[0], a1[1], a1[2], a1[3], b2, b3);
        }
    }

    __syncthreads();   // all warps done with A/B smem (ldmatrix) before Ch overlay

    // stage full 128-row tile into Ch (all 8 warps write their own acc rows)
#pragma unroll
    for (int mt = 0; mt < 2; mt++)
#pragma unroll
        for (int h = 0; h < 2; h++) {
            int rl = wm + mt * 16 + h * 8 + (lane >> 2);
#pragma unroll
            for (int nt = 0; nt < 8; nt++) {
                int col = wn + nt * 8 + 2 * (lane & 3);
                *(float2*)&Ch[rl][col] =
                    make_float2(acc[mt][nt][h * 2 + 0], acc[mt][nt][h * 2 + 1]);
            }
        }
    __syncthreads();

    if (isRoot) {
        // root: coalesced rows — one red.v4 warp-instruction per row (+bias)
        float4 bias4 = ((const float4*)bias)[lane];
        for (int row = wid; row < 128; row += 8) {
            int grow = row0 + row;
            if (grow >= Nn) continue;
            float4 v = *(const float4*)&Ch[row][lane * 4];
            v.x += bias4.x; v.y += bias4.y; v.z += bias4.z; v.w += bias4.w;
            float* p = g_acc + (size_t)grow * 128 + lane * 4;
            asm volatile("red.global.add.v4.f32 [%0], {%1,%2,%3,%4};"
                         :: "l"(p), "f"(v.x), "f"(v.y), "f"(v.z), "f"(v.w) : "memory");
        }
        return;
    }

    // scatter loop over the contiguous bucket pair (unrolled x2, packed metadata)
    int lo = g_boff[bkt0], hi = g_boff[bkt0 + 2];
    int i = lo + wid;
    int2 m0 = make_int2(0, 0), m1 = make_int2(0, 0);
    if (i < hi)     m0 = g_bmeta[i];
    if (i + 8 < hi) m1 = g_bmeta[i + 8];
    while (i < hi) {
        int2 c0 = m0, c1 = m1;
        bool has1 = (i + 8 < hi);
        if (i + 16 < hi) m0 = g_bmeta[i + 16];
        if (i + 24 < hi) m1 = g_bmeta[i + 24];

        {
            int sloc = (c0.x >> 17) & 127;
            int dst  = c0.x & 0x1FFFF;
            float w  = __int_as_float(c0.y);
            float4 v = *(const float4*)&Ch[sloc][lane * 4];
            v.x *= w; v.y *= w; v.z *= w; v.w *= w;
            float* p = g_acc + (size_t)dst * 128 + lane * 4;
            asm volatile("red.global.add.v4.f32 [%0], {%1,%2,%3,%4};"
                         :: "l"(p), "f"(v.x), "f"(v.y), "f"(v.z), "f"(v.w) : "memory");
        }
        if (has1) {
            int sloc = (c1.x >> 17) & 127;
            int dst  = c1.x & 0x1FFFF;
            float w  = __int_as_float(c1.y);
            float4 v = *(const float4*)&Ch[sloc][lane * 4];
            v.x *= w; v.y *= w; v.z *= w; v.w *= w;
            float* p = g_acc + (size_t)dst * 128 + lane * 4;
            asm volatile("red.global.add.v4.f32 [%0], {%1,%2,%3,%4};"
                         :: "l"(p), "f"(v.x), "f"(v.y), "f"(v.z), "f"(v.w) : "memory");
        }
        i += 16;
    }
}

// ---------------- launch ----------------
extern "C" void kernel_launch(void* const* d_in, const int* in_sizes, int n_in,
                              void* d_out, int out_size) {
    const int*   edge_index   = (const int*)d_in[0];
    const int*   edge_type    = (const int*)d_in[1];
    const int*   node_indices = (const int*)d_in[2];
    const float* file_feats   = (const float*)d_in[3];
    const int*   file_idx     = (const int*)d_in[4];
    const float* domain_feats = (const float*)d_in[5];
    const int*   domain_idx   = (const int*)d_in[6];
    const float* ip_feats     = (const float*)d_in[7];
    const int*   ip_idx       = (const int*)d_in[8];
    const float* fallback     = (const float*)d_in[9];
    const float* Wf  = (const float*)d_in[10];
    const float* bf  = (const float*)d_in[11];
    const float* Wd  = (const float*)d_in[12];
    const float* bd  = (const float*)d_in[13];
    const float* Wi  = (const float*)d_in[14];
    const float* bi  = (const float*)d_in[15];
    const float* comp1  = (const float*)d_in[16];
    const float* bases1 = (const float*)d_in[17];
    const float* root1  = (const float*)d_in[18];
    const float* bias1  = (const float*)d_in[19];
    const float* comp2  = (const float*)d_in[20];
    const float* bases2 = (const float*)d_in[21];
    const float* root2  = (const float*)d_in[22];
    const float* bias2  = (const float*)d_in[23];
    const float* ln1_g  = (const float*)d_in[24];
    const float* ln1_b  = (const float*)d_in[25];
    const float* ln2_g  = (const float*)d_in[26];
    const float* ln2_b  = (const float*)d_in[27];
    const float* Wc1 = (const float*)d_in[28];
    const float* bc1 = (const float*)d_in[29];
    const float* Wc2 = (const float*)d_in[30];
    const float* bc2 = (const float*)d_in[31];
    float* out = (float*)d_out;

    static int smem_set = 0;
    if (!smem_set) {
        cudaFuncSetAttribute(ftg_h, cudaFuncAttributeMaxDynamicSharedMemorySize, SMH_TOTAL);
        smem_set = 1;
    }

    // ---- zero counters, then fused proj || copy/acc-zero || count ----
    k_zero<<<(Rr * Nn + 255) / 256, 256>>>();
    k_mega<<<NB_PROJ + NB_COPY + NB_CNT, 256>>>(
        file_feats,   Wf, bf, file_idx,   20000, 256,
        domain_feats, Wd, bd, domain_idx, 15000, 128,
        ip_feats,     Wi, bi, ip_idx,     10000, 64,
        fallback, edge_index, edge_type);

    // ---- both layers' W + bucket scan (fused) ----
    k_setup<<<dim3(NB_BW + 1, 2), 1024>>>(comp1, bases1, root1, comp2, bases2, root2);

    // ---- place edges (packed metadata, 2 edges/thread) ----
    k_place<<<(Ee / 2 + 255) / 256, 256>>>(edge_index, edge_type);

    dim3 fgrid(NTILE, SLOTS);

    // ---- layer 1 ----
    ftg_h<<<fgrid, 256, SMH_TOTAL>>>(bias1, 0);
    k_ln<<<(Nn * 32 + 255) / 256, 256>>>(ln1_g, ln1_b, 1, 1);

    // ---- layer 2 ----
    ftg_h<<<fgrid, 256, SMH_TOTAL>>>(bias2, 1);
    k_ln<<<(Nn * 32 + 255) / 256, 256>>>(ln2_g, ln2_b, 0, 0);

    // ---- classifier ----
    cgemm<<<NSEL / 128, 256>>>(node_indices, Wc1, bc1);
    k_final<<<(NSEL * NCc + 255) / 256, 256>>>(Wc2, bc2, out);
}

// round 17
// speedup vs baseline: 1.4609x; 1.0121x over previous
#include <cuda_runtime.h>
#include <cuda_fp16.h>
#include <cstdint>

// Problem constants
#define Nn    50000
#define Dd    128
#define Rr    10
#define Ee    800000
#define NSEL  8192
#define NCc   12
#define NTILE 391                 // ceil(Nn/128)
#define NG    782                 // ceil(Nn/64) src groups
#define NBKT  (Rr * NG)
#define SLOTS (Rr + 1)            // 10 relations + root

// ftg_h smem: A half[128][136] + B half[128][136]; Ch f32[128][132] overlays A+B
#define SMH_A_BYTES (128 * 136 * 2)     // 34816
#define SMH_TOTAL   (2 * SMH_A_BYTES)   // 69632  (Ch needs 67584 <= this)
#define CH_STRIDE   132

// mega-kernel block ranges
#define NB_PROJ  354      // 157 + 118 + 79
#define NB_COPY  6250     // Nn*Dd/4 / 256
#define NB_CNT   3125     // Ee / 256

// k_setup: build-W blocks (1024 thr) + 1 scan block
#define NB_BW    176      // SLOTS*Dd*Dd / 1024

// ---------------- device scratch ----------------
__device__ __half g_xh[Nn * Dd];              // node features, fp16
__device__ float  g_acc[Nn * Dd];             // conv accumulator (fp32)
__device__ __half g_Wh[2 * SLOTS * Dd * Dd];  // both layers' W^T [layer][slot][n][k]
__device__ int    g_icnt[Rr * Nn];
__device__ float  g_hsel[NSEL * Dd];
__device__ int    g_bcnt[NBKT];
__device__ int    g_bcur[NBKT];               // initialized to boff by scan
__device__ int    g_boff[NBKT + 1];
__device__ int2   g_bmeta[Ee];                // {sloc<<17|dst, f32bits(w)}

// ---------------- helpers ----------------
__device__ __forceinline__ unsigned f2tf(float f) {
    unsigned u;
    asm("cvt.rna.tf32.f32 %0, %1;" : "=r"(u) : "f"(f));
    return u;
}

__device__ __forceinline__ void mma_tf32(float c[4], const unsigned a[4], const unsigned b[2]) {
    asm volatile("mma.sync.aligned.m16n8k8.row.col.f32.tf32.tf32.f32 "
                 "{%0,%1,%2,%3}, {%4,%5,%6,%7}, {%8,%9}, {%0,%1,%2,%3};"
                 : "+f"(c[0]), "+f"(c[1]), "+f"(c[2]), "+f"(c[3])
                 : "r"(a[0]), "r"(a[1]), "r"(a[2]), "r"(a[3]), "r"(b[0]), "r"(b[1]));
}

__device__ __forceinline__ void mma_f16(float c[4], unsigned a0, unsigned a1,
                                        unsigned a2, unsigned a3,
                                        unsigned b0, unsigned b1) {
    asm volatile("mma.sync.aligned.m16n8k16.row.col.f32.f16.f16.f32 "
                 "{%0,%1,%2,%3}, {%4,%5,%6,%7}, {%8,%9}, {%0,%1,%2,%3};"
                 : "+f"(c[0]), "+f"(c[1]), "+f"(c[2]), "+f"(c[3])
                 : "r"(a0), "r"(a1), "r"(a2), "r"(a3), "r"(b0), "r"(b1));
}

__device__ __forceinline__ void cp16(void* smem, const void* g, int srcsize) {
    unsigned a = (unsigned)__cvta_generic_to_shared(smem);
    asm volatile("cp.async.ca.shared.global [%0], [%1], 16, %2;"
                 :: "r"(a), "l"(g), "r"(srcsize));
}

__device__ __forceinline__ void ldsm4(unsigned& r0, unsigned& r1, unsigned& r2, unsigned& r3,
                                      uint32_t addr) {
    asm volatile("ldmatrix.sync.aligned.m8n8.x4.shared.b16 {%0,%1,%2,%3}, [%4];"
                 : "=r"(r0), "=r"(r1), "=r"(r2), "=r"(r3) : "r"(addr));
}

__device__ __forceinline__ uint32_t sma(const void* p) {
    return (uint32_t)__cvta_generic_to_shared(p);
}

// ---------------- small kernels ----------------
__global__ void k_zero() {
    int i = blockIdx.x * blockDim.x + threadIdx.x;
    if (i < Rr * Nn) g_icnt[i] = 0;
    if (i < NBKT) g_bcnt[i] = 0;
}

// fused: builds both layers' W^T (fp16) AND runs the bucket scan in the last block.
// Scan also initializes g_bcur[b] = g_boff[b] (absolute placement cursors).
__global__ void k_setup(const float* __restrict__ comp1, const float* __restrict__ bases1,
                        const float* __restrict__ root1,
                        const float* __restrict__ comp2, const float* __restrict__ bases2,
                        const float* __restrict__ root2) {
    int t = threadIdx.x;
    if (blockIdx.x == NB_BW) {
        if (blockIdx.y != 0) return;
        __shared__ int wsum[32];
        int lane = t & 31, wid = t >> 5;
        int cnt[8];
        int s = 0;
#pragma unroll
        for (int j = 0; j < 8; j++) {
            int b = t * 8 + j;
            cnt[j] = (b < NBKT) ? g_bcnt[b] : 0;
            s += cnt[j];
        }
        int incl = s;
#pragma unroll
        for (int o = 1; o < 32; o <<= 1) {
            int v = __shfl_up_sync(0xffffffffu, incl, o);
            if (lane >= o) incl += v;
        }
        if (lane == 31) wsum[wid] = incl;
        __syncthreads();
        if (wid == 0) {
            int v = wsum[lane];
            int iv = v;
#pragma unroll
            for (int o = 1; o < 32; o <<= 1) {
                int u = __shfl_up_sync(0xffffffffu, iv, o);
                if (lane >= o) iv += u;
            }
            wsum[lane] = iv - v;
            if (lane == 31) g_boff[NBKT] = iv;
        }
        __syncthreads();
        int run = wsum[wid] + (incl - s);
#pragma unroll
        for (int j = 0; j < 8; j++) {
            int b = t * 8 + j;
            if (b < NBKT) { g_boff[b] = run; g_bcur[b] = run; run += cnt[j]; }
        }
        return;
    }
    int i = blockIdx.x * 1024 + t;
    int layer = blockIdx.y;
    const float* comp  = layer ? comp2  : comp1;
    const float* bases = layer ? bases2 : bases1;
    const float* root  = layer ? root2  : root1;
    int slot = i >> 14;
    int idx  = i & 16383;          // n*128 + k
    int n = idx >> 7, k = idx & 127;
    int src = k * 128 + n;
    float v;
    if (slot < Rr) {
        v = 0.f;
#pragma unroll
        for (int b = 0; b < 4; b++)
            v += comp[slot * 4 + b] * bases[b * Dd * Dd + src];
    } else {
        v = root[src];
    }
    g_Wh[layer * SLOTS * Dd * Dd + i] = __float2half_rn(v);
}

// places edges (2 per thread; absolute cursors — no boff load on the chain)
__global__ void k_place(const int* __restrict__ ei, const int* __restrict__ et) {
    int e0 = (blockIdx.x * blockDim.x + threadIdx.x) * 2;
    if (e0 >= Ee) return;
    int e1 = e0 + 1;
    bool has1 = (e1 < Ee);

    int r0 = et[e0], s0 = ei[e0], t0 = ei[Ee + e0];
    int r1 = 0, s1 = 0, t1 = 0;
    if (has1) { r1 = et[e1]; s1 = ei[e1]; t1 = ei[Ee + e1]; }

    int c0 = g_icnt[r0 * Nn + t0];
    int c1 = has1 ? g_icnt[r1 * Nn + t1] : 1;

    int pos0 = atomicAdd(&g_bcur[r0 * NG + (s0 >> 6)], 1);
    float w0 = 1.0f / fmaxf((float)c0, 1.0f);
    g_bmeta[pos0] = make_int2(((s0 & 127) << 17) | t0, __float_as_int(w0));

    if (has1) {
        int pos1 = atomicAdd(&g_bcur[r1 * NG + (s1 >> 6)], 1);
        float w1 = 1.0f / fmaxf((float)c1, 1.0f);
        g_bmeta[pos1] = make_int2(((s1 & 127) << 17) | t1, __float_as_int(w1));
    }
}

// one warp per node: LayerNorm (+optional ReLU) -> g_xh (fp16); optionally zeroes acc
__global__ void k_ln(const float* __restrict__ g, const float* __restrict__ b,
                     int relu, int zeroAcc) {
    int gt = blockIdx.x * blockDim.x + threadIdx.x;
    int node = gt >> 5;
    if (node >= Nn) return;
    int lane = gt & 31;
    float4 v = ((const float4*)g_acc)[node * 32 + lane];
    float s = v.x + v.y + v.z + v.w;
    float q = v.x * v.x + v.y * v.y + v.z * v.z + v.w * v.w;
#pragma unroll
    for (int o = 16; o; o >>= 1) {
        s += __shfl_xor_sync(0xffffffffu, s, o);
        q += __shfl_xor_sync(0xffffffffu, q, o);
    }
    float mean = s * (1.f / 128.f);
    float var  = q * (1.f / 128.f) - mean * mean;
    float rstd = rsqrtf(var + 1e-5f);
    float4 gg = ((const float4*)g)[lane];
    float4 bb = ((const float4*)b)[lane];
    float4 o4;
    o4.x = (v.x - mean) * rstd * gg.x + bb.x;
    o4.y = (v.y - mean) * rstd * gg.y + bb.y;
    o4.z = (v.z - mean) * rstd * gg.z + bb.z;
    o4.w = (v.w - mean) * rstd * gg.w + bb.w;
    if (relu) {
        o4.x = fmaxf(o4.x, 0.f); o4.y = fmaxf(o4.y, 0.f);
        o4.z = fmaxf(o4.z, 0.f); o4.w = fmaxf(o4.w, 0.f);
    }
    __half2 p0 = __halves2half2(__float2half_rn(o4.x), __float2half_rn(o4.y));
    __half2 p1 = __halves2half2(__float2half_rn(o4.z), __float2half_rn(o4.w));
    ((uint2*)g_xh)[node * 32 + lane] = make_uint2(*(unsigned*)&p0, *(unsigned*)&p1);
    if (zeroAcc)
        ((float4*)g_acc)[node * 32 + lane] = make_float4(0.f, 0.f, 0.f, 0.f);
}

__global__ void k_final(const float* __restrict__ W, const float* __restrict__ b,
                        float* __restrict__ out) {
    int gt = blockIdx.x * blockDim.x + threadIdx.x;
    if (gt >= NSEL * NCc) return;
    int i = gt / NCc, c = gt % NCc;
    const float* hr = g_hsel + i * Dd;
    float s = b[c];
#pragma unroll 8
    for (int k = 0; k < Dd; k++) s += hr[k] * W[k * NCc + c];
    out[gt] = s;
}

// ---------------- mega kernel: proj (3 segs) || fallback-copy+acc-zero || edge-count --
__global__ void __launch_bounds__(256)
k_mega(const float* A0, const float* W0, const float* b0, const int* x0, int M0, int K0,
       const float* A1, const float* W1, const float* b1, const int* x1, int M1, int K1,
       const float* A2, const float* W2, const float* b2, const int* x2, int M2, int K2,
       const float* __restrict__ fallback,
       const int* __restrict__ ei, const int* __restrict__ et) {
    int blk = blockIdx.x;
    int tid = threadIdx.x;

    if (blk >= NB_PROJ) {
        if (blk < NB_PROJ + NB_COPY) {
            int i = (blk - NB_PROJ) * 256 + tid;
            if (i < Nn * Dd / 4) {
                if (i >= 45000 * 32) {
                    float4 v = ((const float4*)fallback)[i];
                    __half2 p0 = __halves2half2(__float2half_rn(v.x), __float2half_rn(v.y));
                    __half2 p1 = __halves2half2(__float2half_rn(v.z), __float2half_rn(v.w));
                    ((uint2*)g_xh)[i] = make_uint2(*(unsigned*)&p0, *(unsigned*)&p1);
                }
                ((float4*)g_acc)[i] = make_float4(0.f, 0.f, 0.f, 0.f);
            }
        } else {
            int e = (blk - NB_PROJ - NB_COPY) * 256 + tid;
            if (e < Ee) {
                int r = et[e];
                atomicAdd(&g_icnt[r * Nn + ei[Ee + e]], 1);
                atomicAdd(&g_bcnt[r * NG + (ei[e] >> 6)], 1);
            }
        }
        return;
    }

    // ---- projection GEMM segment ----
    const float *A, *B, *bias;
    const int* rowIdx;
    int M, K, row0;
    if (blk < 157)      { A = A0; B = W0; bias = b0; rowIdx = x0; M = M0; K = K0; row0 = blk * 128; }
    else if (blk < 275) { A = A1; B = W1; bias = b1; rowIdx = x1; M = M1; K = K1; row0 = (blk - 157) * 128; }
    else                { A = A2; B = W2; bias = b2; rowIdx = x2; M = M2; K = K2; row0 = (blk - 275) * 128; }

    __shared__ unsigned As[128][36];
    __shared__ unsigned Bs[32][136];
    float acc[2][8][4];
#pragma unroll
    for (int mt = 0; mt < 2; mt++)
#pragma unroll
        for (int nt = 0; nt < 8; nt++)
#pragma unroll
            for (int q = 0; q < 4; q++) acc[mt][nt][q] = 0.f;

    int lane = tid & 31, wid = tid >> 5;
    int wm = (wid >> 1) * 32;
    int wn = (wid & 1) * 64;

    for (int kb = 0; kb < K; kb += 32) {
#pragma unroll
        for (int it = 0; it < 4; it++) {
            int idx = tid + it * 256;
            int m = idx >> 3;
            int kq = (idx & 7) * 4;
            float4 v = make_float4(0.f, 0.f, 0.f, 0.f);
            int row = row0 + m;
            if (row < M) v = *(const float4*)&A[(size_t)row * K + kb + kq];
            As[m][kq + 0] = f2tf(v.x); As[m][kq + 1] = f2tf(v.y);
            As[m][kq + 2] = f2tf(v.z); As[m][kq + 3] = f2tf(v.w);
        }
#pragma unroll
        for (int it = 0; it < 4; it++) {
            int idx = tid + it * 256;
            int k = idx >> 5;
            int nq = (idx & 31) * 4;
            float4 v = *(const float4*)&B[(size_t)(kb + k) * 128 + nq];
            Bs[k][nq + 0] = f2tf(v.x); Bs[k][nq + 1] = f2tf(v.y);
            Bs[k][nq + 2] = f2tf(v.z); Bs[k][nq + 3] = f2tf(v.w);
        }
        __syncthreads();
#pragma unroll
        for (int ks = 0; ks < 4; ks++) {
            int k0 = ks * 8;
            unsigned af[2][4];
#pragma unroll
            for (int mt = 0; mt < 2; mt++) {
                int r = wm + mt * 16 + (lane >> 2);
                int c = k0 + (lane & 3);
                af[mt][0] = As[r][c];     af[mt][1] = As[r + 8][c];
                af[mt][2] = As[r][c + 4]; af[mt][3] = As[r + 8][c + 4];
            }
#pragma unroll
            for (int nt = 0; nt < 8; nt++) {
                unsigned bf[2];
                int br = k0 + (lane & 3);
                int bc = wn + nt * 8 + (lane >> 2);
                bf[0] = Bs[br][bc];
                bf[1] = Bs[br + 4][bc];
                mma_tf32(acc[0][nt], af[0], bf);
                mma_tf32(acc[1][nt], af[1], bf);
            }
        }
        __syncthreads();
    }

#pragma unroll
    for (int mt = 0; mt < 2; mt++) {
#pragma unroll
        for (int h = 0; h < 2; h++) {
            int row = row0 + wm + mt * 16 + (lane >> 2) + h * 8;
            if (row >= M) continue;
            int cr = rowIdx[row];
#pragma unroll
            for (int nt = 0; nt < 8; nt++) {
                int col = wn + nt * 8 + 2 * (lane & 3);
                float v0 = acc[mt][nt][h * 2 + 0] + bias[col];
                float v1 = acc[mt][nt][h * 2 + 1] + bias[col + 1];
                __half2 p = __halves2half2(__float2half_rn(v0), __float2half_rn(v1));
                *(unsigned*)&g_xh[(size_t)cr * 128 + col] = *(unsigned*)&p;
            }
        }
    }
}

// ---------------- classifier GEMM: half input (exact cvt), tf32 math, f32 out ----
__global__ void __launch_bounds__(256)
cgemm(const int* __restrict__ aIdx, const float* __restrict__ B,
      const float* __restrict__ bias) {
    int row0 = blockIdx.x * 128;
    __shared__ unsigned As[128][36];
    __shared__ unsigned Bs[32][136];
    float acc[2][8][4];
#pragma unroll
    for (int mt = 0; mt < 2; mt++)
#pragma unroll
        for (int nt = 0; nt < 8; nt++)
#pragma unroll
            for (int q = 0; q < 4; q++) acc[mt][nt][q] = 0.f;

    int tid = threadIdx.x;
    int lane = tid & 31, wid = tid >> 5;
    int wm = (wid >> 1) * 32;
    int wn = (wid & 1) * 64;

    for (int kb = 0; kb < 128; kb += 32) {
#pragma unroll
        for (int it = 0; it < 4; it++) {
            int idx = tid + it * 256;
            int m = idx >> 3;
            int kq = (idx & 7) * 4;
            int row = row0 + m;
            int ar = aIdx[row];
            const __half* src = &g_xh[(size_t)ar * 128 + kb + kq];
            As[m][kq + 0] = f2tf(__half2float(src[0]));
            As[m][kq + 1] = f2tf(__half2float(src[1]));
            As[m][kq + 2] = f2tf(__half2float(src[2]));
            As[m][kq + 3] = f2tf(__half2float(src[3]));
        }
#pragma unroll
        for (int it = 0; it < 4; it++) {
            int idx = tid + it * 256;
            int k = idx >> 5;
            int nq = (idx & 31) * 4;
            float4 v = *(const float4*)&B[(size_t)(kb + k) * 128 + nq];
            Bs[k][nq + 0] = f2tf(v.x); Bs[k][nq + 1] = f2tf(v.y);
            Bs[k][nq + 2] = f2tf(v.z); Bs[k][nq + 3] = f2tf(v.w);
        }
        __syncthreads();
#pragma unroll
        for (int ks = 0; ks < 4; ks++) {
            int k0 = ks * 8;
            unsigned af[2][4];
#pragma unroll
            for (int mt = 0; mt < 2; mt++) {
                int r = wm + mt * 16 + (lane >> 2);
                int c = k0 + (lane & 3);
                af[mt][0] = As[r][c];     af[mt][1] = As[r + 8][c];
                af[mt][2] = As[r][c + 4]; af[mt][3] = As[r + 8][c + 4];
            }
#pragma unroll
            for (int nt = 0; nt < 8; nt++) {
                unsigned bf[2];
                int br = k0 + (lane & 3);
                int bc = wn + nt * 8 + (lane >> 2);
                bf[0] = Bs[br][bc];
                bf[1] = Bs[br + 4][bc];
                mma_tf32(acc[0][nt], af[0], bf);
                mma_tf32(acc[1][nt], af[1], bf);
            }
        }
        __syncthreads();
    }

#pragma unroll
    for (int mt = 0; mt < 2; mt++) {
#pragma unroll
        for (int h = 0; h < 2; h++) {
            int row = row0 + wm + mt * 16 + (lane >> 2) + h * 8;
#pragma unroll
            for (int nt = 0; nt < 8; nt++) {
                int col = wn + nt * 8 + 2 * (lane & 3);
                float v0 = fmaxf(acc[mt][nt][h * 2 + 0] + bias[col], 0.f);
                float v1 = fmaxf(acc[mt][nt][h * 2 + 1] + bias[col + 1], 0.f);
                *(float2*)&g_hsel[(size_t)row * 128 + col] = make_float2(v0, v1);
            }
        }
    }
}

// ---------------- fp16 fused dense GEMM + edge scatter (single-phase epilogue) ------
// grid = (NTILE, SLOTS) — 4301 independent blocks: cross-block MMA/scatter overlap.
__global__ void __launch_bounds__(256, 2)
ftg_h(const float* __restrict__ bias, int layer) {
    extern __shared__ __align__(16) char dsm[];
    __half (*As)[136] = (__half(*)[136])dsm;
    __half (*Bs)[136] = (__half(*)[136])(dsm + SMH_A_BYTES);
    float  (*Ch)[CH_STRIDE] = (float(*)[CH_STRIDE])dsm;   // overlays A+B after MMA

    int tile = blockIdx.x;
    int r    = blockIdx.y;
    int row0 = tile * 128;
    bool isRoot = (r == Rr);

    int lo = 0, hi = 0;
    if (!isRoot) {
        int bkt0 = r * NG + tile * 2;
        lo = g_boff[bkt0];
        hi = g_boff[bkt0 + 2];
        if (lo == hi) return;
    }

    int tid = threadIdx.x;
    int lane = tid & 31, wid = tid >> 5;
    int wm = (wid >> 1) * 32;
    int wn = (wid & 1) * 64;

    const __half* Wz = g_Wh + (size_t)(layer * SLOTS + r) * (Dd * Dd);

#pragma unroll
    for (int it = 0; it < 8; it++) {
        int idx = tid + it * 256;
        int m = idx >> 4, c8 = (idx & 15) * 8;
        int gr = row0 + m;
        cp16(&As[m][c8], &g_xh[(size_t)gr * 128 + c8], gr < Nn ? 16 : 0);
    }
#pragma unroll
    for (int it = 0; it < 8; it++) {
        int idx = tid + it * 256;
        int n = idx >> 4, c8 = (idx & 15) * 8;
        cp16(&Bs[n][c8], &Wz[(size_t)n * 128 + c8], 16);
    }
    asm volatile("cp.async.commit_group;");

    float acc[2][8][4];
#pragma unroll
    for (int mt = 0; mt < 2; mt++)
#pragma unroll
        for (int nt = 0; nt < 8; nt++)
#pragma unroll
            for (int q = 0; q < 4; q++) acc[mt][nt][q] = 0.f;

    // ldmatrix base addresses
    int l7 = lane & 7, lm = (lane >> 3) & 1, lh = lane >> 4;
    uint32_t aAddr[2], bAddr[4];
#pragma unroll
    for (int mt = 0; mt < 2; mt++)
        aAddr[mt] = sma(&As[wm + mt * 16 + lm * 8 + l7][lh * 8]);
#pragma unroll
    for (int p = 0; p < 4; p++)
        bAddr[p] = sma(&Bs[wn + (2 * p + lh) * 8 + l7][lm * 8]);

    asm volatile("cp.async.wait_group 0;" ::: "memory");
    __syncthreads();

#pragma unroll
    for (int ks = 0; ks < 8; ks++) {
        uint32_t off = ks * 32;
        unsigned a0[4], a1[4];
        ldsm4(a0[0], a0[1], a0[2], a0[3], aAddr[0] + off);
        ldsm4(a1[0], a1[1], a1[2], a1[3], aAddr[1] + off);
#pragma unroll
        for (int p = 0; p < 4; p++) {
            unsigned b0, b1, b2, b3;
            ldsm4(b0, b1, b2, b3, bAddr[p] + off);
            mma_f16(acc[0][2 * p + 0], a0[0], a0[1], a0[2], a0[3], b0, b1);
            mma_f16(acc[0][2 * p + 1], a0[0], a0[1], a0[2], a0[3], b2, b3);
            mma_f16(acc[1][2 * p + 0], a1[0], a1[1], a1[2], a1[3], b0, b1);
            mma_f16(acc[1][2 * p + 1], a1[0], a1[1], a1[2], a1[3], b2, b3);
        }
    }

    // pre-issue first scatter metadata loads (in flight across the staging barriers)
    int i = lo + wid;
    int2 m0 = make_int2(0, 0), m1 = make_int2(0, 0);
    if (!isRoot) {
        if (i < hi)     m0 = g_bmeta[i];
        if (i + 8 < hi) m1 = g_bmeta[i + 8];
    }

    __syncthreads();   // all warps done with A/B smem (ldmatrix) before Ch overlay

    // stage full 128-row tile into Ch (all 8 warps write their own acc rows)
#pragma unroll
    for (int mt = 0; mt < 2; mt++)
#pragma unroll
        for (int h = 0; h < 2; h++) {
            int rl = wm + mt * 16 + h * 8 + (lane >> 2);
#pragma unroll
            for (int nt = 0; nt < 8; nt++) {
                int col = wn + nt * 8 + 2 * (lane & 3);
                *(float2*)&Ch[rl][col] =
                    make_float2(acc[mt][nt][h * 2 + 0], acc[mt][nt][h * 2 + 1]);
            }
        }
    __syncthreads();

    if (isRoot) {
        // root: coalesced rows — one red.v4 warp-instruction per row (+bias)
        float4 bias4 = ((const float4*)bias)[lane];
        for (int row = wid; row < 128; row += 8) {
            int grow = row0 + row;
            if (grow >= Nn) continue;
            float4 v = *(const float4*)&Ch[row][lane * 4];
            v.x += bias4.x; v.y += bias4.y; v.z += bias4.z; v.w += bias4.w;
            float* p = g_acc + (size_t)grow * 128 + lane * 4;
            asm volatile("red.global.add.v4.f32 [%0], {%1,%2,%3,%4};"
                         :: "l"(p), "f"(v.x), "f"(v.y), "f"(v.z), "f"(v.w) : "memory");
        }
        return;
    }

    // scatter loop over the contiguous bucket pair (unrolled x2, packed metadata)
    while (i < hi) {
        int2 c0 = m0, c1 = m1;
        bool has1 = (i + 8 < hi);
        if (i + 16 < hi) m0 = g_bmeta[i + 16];
        if (i + 24 < hi) m1 = g_bmeta[i + 24];

        {
            int sloc = (c0.x >> 17) & 127;
            int dst  = c0.x & 0x1FFFF;
            float w  = __int_as_float(c0.y);
            float4 v = *(const float4*)&Ch[sloc][lane * 4];
            v.x *= w; v.y *= w; v.z *= w; v.w *= w;
            float* p = g_acc + (size_t)dst * 128 + lane * 4;
            asm volatile("red.global.add.v4.f32 [%0], {%1,%2,%3,%4};"
                         :: "l"(p), "f"(v.x), "f"(v.y), "f"(v.z), "f"(v.w) : "memory");
        }
        if (has1) {
            int sloc = (c1.x >> 17) & 127;
            int dst  = c1.x & 0x1FFFF;
            float w  = __int_as_float(c1.y);
            float4 v = *(const float4*)&Ch[sloc][lane * 4];
            v.x *= w; v.y *= w; v.z *= w; v.w *= w;
            float* p = g_acc + (size_t)dst * 128 + lane * 4;
            asm volatile("red.global.add.v4.f32 [%0], {%1,%2,%3,%4};"
                         :: "l"(p), "f"(v.x), "f"(v.y), "f"(v.z), "f"(v.w) : "memory");
        }
        i += 16;
    }
}

// ---------------- launch ----------------
extern "C" void kernel_launch(void* const* d_in, const int* in_sizes, int n_in,
                              void* d_out, int out_size) {
    const int*   edge_index   = (const int*)d_in[0];
    const int*   edge_type    = (const int*)d_in[1];
    const int*   node_indices = (const int*)d_in[2];
    const float* file_feats   = (const float*)d_in[3];
    const int*   file_idx     = (const int*)d_in[4];
    const float* domain_feats = (const float*)d_in[5];
    const int*   domain_idx   = (const int*)d_in[6];
    const float* ip_feats     = (const float*)d_in[7];
    const int*   ip_idx       = (const int*)d_in[8];
    const float* fallback     = (const float*)d_in[9];
    const float* Wf  = (const float*)d_in[10];
    const float* bf  = (const float*)d_in[11];
    const float* Wd  = (const float*)d_in[12];
    const float* bd  = (const float*)d_in[13];
    const float* Wi  = (const float*)d_in[14];
    const float* bi  = (const float*)d_in[15];
    const float* comp1  = (const float*)d_in[16];
    const float* bases1 = (const float*)d_in[17];
    const float* root1  = (const float*)d_in[18];
    const float* bias1  = (const float*)d_in[19];
    const float* comp2  = (const float*)d_in[20];
    const float* bases2 = (const float*)d_in[21];
    const float* root2  = (const float*)d_in[22];
    const float* bias2  = (const float*)d_in[23];
    const float* ln1_g  = (const float*)d_in[24];
    const float* ln1_b  = (const float*)d_in[25];
    const float* ln2_g  = (const float*)d_in[26];
    const float* ln2_b  = (const float*)d_in[27];
    const float* Wc1 = (const float*)d_in[28];
    const float* bc1 = (const float*)d_in[29];
    const float* Wc2 = (const float*)d_in[30];
    const float* bc2 = (const float*)d_in[31];
    float* out = (float*)d_out;

    static int smem_set = 0;
    if (!smem_set) {
        cudaFuncSetAttribute(ftg_h, cudaFuncAttributeMaxDynamicSharedMemorySize, SMH_TOTAL);
        smem_set = 1;
    }

    // ---- zero counters, then fused proj || copy/acc-zero || count ----
    k_zero<<<(Rr * Nn + 255) / 256, 256>>>();
    k_mega<<<NB_PROJ + NB_COPY + NB_CNT, 256>>>(
        file_feats,   Wf, bf, file_idx,   20000, 256,
        domain_feats, Wd, bd, domain_idx, 15000, 128,
        ip_feats,     Wi, bi, ip_idx,     10000, 64,
        fallback, edge_index, edge_type);

    // ---- both layers' W + bucket scan (fused; scan seeds absolute cursors) ----
    k_setup<<<dim3(NB_BW + 1, 2), 1024>>>(comp1, bases1, root1, comp2, bases2, root2);

    // ---- place edges (packed metadata, 2 edges/thread) ----
    k_place<<<(Ee / 2 + 255) / 256, 256>>>(edge_index, edge_type);

    dim3 fgrid(NTILE, SLOTS);

    // ---- layer 1 ----
    ftg_h<<<fgrid, 256, SMH_TOTAL>>>(bias1, 0);
    k_ln<<<(Nn * 32 + 255) / 256, 256>>>(ln1_g, ln1_b, 1, 1);

    // ---- layer 2 ----
    ftg_h<<<fgrid, 256, SMH_TOTAL>>>(bias2, 1);
    k_ln<<<(Nn * 32 + 255) / 256, 256>>>(ln2_g, ln2_b, 0, 0);

    // ---- classifier ----
    cgemm<<<NSEL / 128, 256>>>(node_indices, Wc1, bc1);
    k_final<<<(NSEL * NCc + 255) / 256, 256>>>(Wc2, bc2, out);
}